// round 4
// baseline (speedup 1.0000x reference)
#include <cuda_runtime.h>
#include <math.h>

#define B_  4
#define S_  2048
#define D_  1024
#define H_  16
#define DK_ 64
#define M_  (B_*S_)   // 8192

// ---------------- scratch (device globals: allocation-free) ----------------
__device__ float g_Qp[M_*D_];
__device__ float g_Kp[M_*D_];
__device__ float g_Vp[M_*D_];
__device__ float g_Op[M_*D_];

// ---------------------------------------------------------------------------
// C[M,N] = A[M,K] @ W[N,K]^T + bias[N]    (M=8192, N=K=1024, all multiples)
// 128x128 block tile, BK=8, 8x8 per-thread register tile, 256 threads.
// ---------------------------------------------------------------------------
__global__ __launch_bounds__(256)
void sgemm_wt_bias(const float* __restrict__ A, const float* __restrict__ W,
                   const float* __restrict__ bias, float* __restrict__ C)
{
    const int N = D_, K = D_;
    __shared__ float As[8][128];
    __shared__ float Bs[8][128];
    const int tid  = threadIdx.x;
    const int brow = blockIdx.y * 128;
    const int bcol = blockIdx.x * 128;
    const int lr   = tid >> 1;          // 0..127
    const int lc   = (tid & 1) << 2;    // 0 or 4
    const int ty   = tid >> 4;          // 0..15
    const int tx   = tid & 15;          // 0..15

    const float* Ag = A + (size_t)(brow + lr) * K + lc;
    const float* Wg = W + (size_t)(bcol + lr) * K + lc;

    float acc[8][8];
    #pragma unroll
    for (int i = 0; i < 8; i++)
        #pragma unroll
        for (int j = 0; j < 8; j++) acc[i][j] = 0.f;

    for (int k0 = 0; k0 < K; k0 += 8) {
        float4 a4 = *(const float4*)(Ag + k0);
        float4 b4 = *(const float4*)(Wg + k0);
        As[lc+0][lr] = a4.x; As[lc+1][lr] = a4.y;
        As[lc+2][lr] = a4.z; As[lc+3][lr] = a4.w;
        Bs[lc+0][lr] = b4.x; Bs[lc+1][lr] = b4.y;
        Bs[lc+2][lr] = b4.z; Bs[lc+3][lr] = b4.w;
        __syncthreads();
        #pragma unroll
        for (int kk = 0; kk < 8; kk++) {
            float ra[8], rb[8];
            *(float4*)&ra[0] = *(const float4*)&As[kk][ty*8];
            *(float4*)&ra[4] = *(const float4*)&As[kk][ty*8+4];
            *(float4*)&rb[0] = *(const float4*)&Bs[kk][tx*8];
            *(float4*)&rb[4] = *(const float4*)&Bs[kk][tx*8+4];
            #pragma unroll
            for (int i = 0; i < 8; i++)
                #pragma unroll
                for (int j = 0; j < 8; j++)
                    acc[i][j] += ra[i] * rb[j];
        }
        __syncthreads();
    }

    float bv[8];
    #pragma unroll
    for (int j = 0; j < 8; j++) bv[j] = bias[bcol + tx*8 + j];
    #pragma unroll
    for (int i = 0; i < 8; i++) {
        float* Cp = C + (size_t)(brow + ty*8 + i) * N + bcol + tx*8;
        float4 o0 = make_float4(acc[i][0]+bv[0], acc[i][1]+bv[1],
                                acc[i][2]+bv[2], acc[i][3]+bv[3]);
        float4 o1 = make_float4(acc[i][4]+bv[4], acc[i][5]+bv[5],
                                acc[i][6]+bv[6], acc[i][7]+bv[7]);
        *(float4*)Cp     = o0;
        *(float4*)(Cp+4) = o1;
    }
}

// ---------------------------------------------------------------------------
// Causal flash attention, fp32. Block = (q-tile of 64 rows, one (b,h)).
// 256 threads = 16x16; 4x4 register tiles for S=QK^T and O+=P·V.
// Q,K stored k-major-transposed in smem; V,P natural. Online softmax with
// 16-lane shfl reductions (row owned by 16 tx-lanes).
// ---------------------------------------------------------------------------
#define PQ 68
#define SMEM_FLOATS (4*64*PQ)

__global__ __launch_bounds__(256)
void flash_attn(const float* __restrict__ Qp, const float* __restrict__ Kp,
                const float* __restrict__ Vp, float* __restrict__ Op)
{
    extern __shared__ float sm[];
    float* smQ = sm;
    float* smK = sm + 64*PQ;
    float* smV = sm + 2*64*PQ;
    float* smP = sm + 3*64*PQ;

    const int tid = threadIdx.x;
    const int ty  = tid >> 4;
    const int tx  = tid & 15;
    const int qt  = blockIdx.x;
    const int q0  = qt * 64;
    const int b   = blockIdx.y >> 4;
    const int h   = blockIdx.y & 15;

    const size_t headoff = (size_t)h * DK_;
    const float* Qg = Qp + ((size_t)(b*S_) + q0) * D_ + headoff;

    // Load Q tile transposed into smem, pre-scaled by 1/sqrt(DK)
    for (int i = tid; i < 64*16; i += 256) {
        int r = i >> 4, k4 = (i & 15) << 2;
        float4 v = *(const float4*)(Qg + (size_t)r * D_ + k4);
        smQ[(k4+0)*PQ + r] = v.x * 0.125f;
        smQ[(k4+1)*PQ + r] = v.y * 0.125f;
        smQ[(k4+2)*PQ + r] = v.z * 0.125f;
        smQ[(k4+3)*PQ + r] = v.w * 0.125f;
    }

    float m_i[4], l_i[4], o[4][4];
    #pragma unroll
    for (int i = 0; i < 4; i++) {
        m_i[i] = -INFINITY; l_i[i] = 0.f;
        #pragma unroll
        for (int j = 0; j < 4; j++) o[i][j] = 0.f;
    }

    for (int t = 0; t <= qt; t++) {
        const float* Kg = Kp + ((size_t)(b*S_) + t*64) * D_ + headoff;
        const float* Vg = Vp + ((size_t)(b*S_) + t*64) * D_ + headoff;
        __syncthreads();   // previous iteration done with smK/smV
        for (int i = tid; i < 64*16; i += 256) {
            int r = i >> 4, k4 = (i & 15) << 2;
            float4 kv = *(const float4*)(Kg + (size_t)r * D_ + k4);
            smK[(k4+0)*PQ + r] = kv.x;
            smK[(k4+1)*PQ + r] = kv.y;
            smK[(k4+2)*PQ + r] = kv.z;
            smK[(k4+3)*PQ + r] = kv.w;
            float4 vv = *(const float4*)(Vg + (size_t)r * D_ + k4);
            *(float4*)&smV[r*PQ + k4] = vv;
        }
        __syncthreads();

        // S = (Q*scale) @ K^T   (4x4 per thread)
        float s[4][4];
        #pragma unroll
        for (int i = 0; i < 4; i++)
            #pragma unroll
            for (int j = 0; j < 4; j++) s[i][j] = 0.f;

        #pragma unroll 16
        for (int kk = 0; kk < 64; kk++) {
            float ra[4], rb[4];
            *(float4*)ra = *(const float4*)&smQ[kk*PQ + ty*4];
            *(float4*)rb = *(const float4*)&smK[kk*PQ + tx*4];
            #pragma unroll
            for (int i = 0; i < 4; i++)
                #pragma unroll
                for (int j = 0; j < 4; j++)
                    s[i][j] += ra[i] * rb[j];
        }

        if (t == qt) {  // diagonal tile: mask col > row
            #pragma unroll
            for (int i = 0; i < 4; i++)
                #pragma unroll
                for (int j = 0; j < 4; j++)
                    if (tx*4 + j > ty*4 + i) s[i][j] = -INFINITY;
        }

        // online softmax update (row stats replicated across 16 tx lanes)
        #pragma unroll
        for (int i = 0; i < 4; i++) {
            float rm = fmaxf(fmaxf(s[i][0], s[i][1]), fmaxf(s[i][2], s[i][3]));
            rm = fmaxf(rm, __shfl_xor_sync(0xffffffffu, rm, 1));
            rm = fmaxf(rm, __shfl_xor_sync(0xffffffffu, rm, 2));
            rm = fmaxf(rm, __shfl_xor_sync(0xffffffffu, rm, 4));
            rm = fmaxf(rm, __shfl_xor_sync(0xffffffffu, rm, 8));
            float mnew  = fmaxf(m_i[i], rm);
            float alpha = __expf(m_i[i] - mnew);
            m_i[i] = mnew;
            float rs = 0.f;
            #pragma unroll
            for (int j = 0; j < 4; j++) {
                float p = __expf(s[i][j] - mnew);
                s[i][j] = p; rs += p;
            }
            rs += __shfl_xor_sync(0xffffffffu, rs, 1);
            rs += __shfl_xor_sync(0xffffffffu, rs, 2);
            rs += __shfl_xor_sync(0xffffffffu, rs, 4);
            rs += __shfl_xor_sync(0xffffffffu, rs, 8);
            l_i[i] = l_i[i]*alpha + rs;
            #pragma unroll
            for (int j = 0; j < 4; j++) o[i][j] *= alpha;
            *(float4*)&smP[(ty*4+i)*PQ + tx*4] =
                make_float4(s[i][0], s[i][1], s[i][2], s[i][3]);
        }
        __syncthreads();

        // O += P @ V   (4x4 per thread)
        #pragma unroll 4
        for (int j0 = 0; j0 < 64; j0 += 4) {
            float rp[4][4], rv[4][4];
            #pragma unroll
            for (int i = 0; i < 4; i++)
                *(float4*)rp[i] = *(const float4*)&smP[(ty*4+i)*PQ + j0];
            #pragma unroll
            for (int u = 0; u < 4; u++)
                *(float4*)rv[u] = *(const float4*)&smV[(j0+u)*PQ + tx*4];
            #pragma unroll
            for (int i = 0; i < 4; i++)
                #pragma unroll
                for (int j = 0; j < 4; j++)
                    o[i][j] += rp[i][0]*rv[0][j] + rp[i][1]*rv[1][j]
                             + rp[i][2]*rv[2][j] + rp[i][3]*rv[3][j];
        }
    }

    // normalize and store
    float* Og = Op + ((size_t)(b*S_) + q0) * D_ + headoff;
    #pragma unroll
    for (int i = 0; i < 4; i++) {
        float inv = 1.f / l_i[i];
        *(float4*)(Og + (size_t)(ty*4+i)*D_ + tx*4) =
            make_float4(o[i][0]*inv, o[i][1]*inv, o[i][2]*inv, o[i][3]*inv);
    }
}

// ---------------------------------------------------------------------------
extern "C" void kernel_launch(void* const* d_in, const int* in_sizes, int n_in,
                              void* d_out, int out_size)
{
    const float* q  = (const float*)d_in[0];
    const float* k  = (const float*)d_in[1];
    const float* v  = (const float*)d_in[2];
    const float* Wq = (const float*)d_in[3];
    const float* bq = (const float*)d_in[4];
    const float* Wk = (const float*)d_in[5];
    const float* bk = (const float*)d_in[6];
    const float* Wv = (const float*)d_in[7];
    const float* bv = (const float*)d_in[8];
    const float* Wo = (const float*)d_in[9];
    const float* bo = (const float*)d_in[10];
    // d_in[11] = causal_mask: causality computed analytically, not read
    float* out = (float*)d_out;

    float *Qp, *Kp, *Vp, *Op;
    cudaGetSymbolAddress((void**)&Qp, g_Qp);
    cudaGetSymbolAddress((void**)&Kp, g_Kp);
    cudaGetSymbolAddress((void**)&Vp, g_Vp);
    cudaGetSymbolAddress((void**)&Op, g_Op);

    dim3 gg(D_/128, M_/128);
    sgemm_wt_bias<<<gg, 256>>>(q, Wq, bq, Qp);
    sgemm_wt_bias<<<gg, 256>>>(k, Wk, bk, Kp);
    sgemm_wt_bias<<<gg, 256>>>(v, Wv, bv, Vp);

    const int smem = SMEM_FLOATS * (int)sizeof(float);   // 69632 B
    cudaFuncSetAttribute(flash_attn,
                         cudaFuncAttributeMaxDynamicSharedMemorySize, smem);
    flash_attn<<<dim3(S_/64, B_*H_), 256, smem>>>(Qp, Kp, Vp, Op);

    sgemm_wt_bias<<<gg, 256>>>(Op, Wo, bo, out);
}

// round 6
// speedup vs baseline: 1.0226x; 1.0226x over previous
#include <cuda_runtime.h>
#include <math.h>

#define B_  4
#define S_  2048
#define D_  1024
#define H_  16
#define DK_ 64
#define M_  (B_*S_)   // 8192

typedef unsigned long long u64;

// packed fp32x2 helpers (Blackwell sm_103a; exact fp32 semantics, 2x FFMA rate)
__device__ __forceinline__ u64 pk2(float lo, float hi) {
    u64 r; asm("mov.b64 %0, {%1, %2};" : "=l"(r) : "f"(lo), "f"(hi)); return r;
}
__device__ __forceinline__ u64 pkdup(float v) { return pk2(v, v); }
__device__ __forceinline__ void unpk2(float& lo, float& hi, u64 v) {
    asm("mov.b64 {%0, %1}, %2;" : "=f"(lo), "=f"(hi) : "l"(v));
}
__device__ __forceinline__ u64 fma2(u64 a, u64 b, u64 c) {
    u64 d; asm("fma.rn.f32x2 %0, %1, %2, %3;" : "=l"(d) : "l"(a), "l"(b), "l"(c)); return d;
}
__device__ __forceinline__ u64 mul2(u64 a, u64 b) {
    u64 d; asm("mul.rn.f32x2 %0, %1, %2;" : "=l"(d) : "l"(a), "l"(b)); return d;
}

// ---------------- scratch (device globals: allocation-free) ----------------
__device__ float g_Qp[M_*D_];
__device__ float g_Kp[M_*D_];
__device__ float g_Vp[M_*D_];
__device__ float g_Op[M_*D_];

// ---------------------------------------------------------------------------
// C[M,N] = A[M,K] @ W[N,K]^T + bias[N]    (M=8192, N=K=1024)
// 128x128 block tile, BK=8, 8x8 per-thread register tile, 256 threads.
// Inner product done with fma.rn.f32x2 (j-pairs packed).
// ---------------------------------------------------------------------------
__global__ __launch_bounds__(256)
void sgemm_wt_bias(const float* __restrict__ A, const float* __restrict__ W,
                   const float* __restrict__ bias, float* __restrict__ C)
{
    const int N = D_, K = D_;
    __shared__ float As[8][128];
    __shared__ float Bs[8][128];
    const int tid  = threadIdx.x;
    const int brow = blockIdx.y * 128;
    const int bcol = blockIdx.x * 128;
    const int lr   = tid >> 1;          // 0..127
    const int lc   = (tid & 1) << 2;    // 0 or 4
    const int ty   = tid >> 4;          // 0..15
    const int tx   = tid & 15;          // 0..15

    const float* Ag = A + (size_t)(brow + lr) * K + lc;
    const float* Wg = W + (size_t)(bcol + lr) * K + lc;

    u64 acc2[8][4];
    #pragma unroll
    for (int i = 0; i < 8; i++)
        #pragma unroll
        for (int jp = 0; jp < 4; jp++) acc2[i][jp] = 0ULL;   // (0.f, 0.f)

    for (int k0 = 0; k0 < K; k0 += 8) {
        float4 a4 = *(const float4*)(Ag + k0);
        float4 b4 = *(const float4*)(Wg + k0);
        As[lc+0][lr] = a4.x; As[lc+1][lr] = a4.y;
        As[lc+2][lr] = a4.z; As[lc+3][lr] = a4.w;
        Bs[lc+0][lr] = b4.x; Bs[lc+1][lr] = b4.y;
        Bs[lc+2][lr] = b4.z; Bs[lc+3][lr] = b4.w;
        __syncthreads();
        #pragma unroll
        for (int kk = 0; kk < 8; kk++) {
            float4 a0 = *(const float4*)&As[kk][ty*8];
            float4 a1 = *(const float4*)&As[kk][ty*8+4];
            ulonglong2 b01 = *(const ulonglong2*)&Bs[kk][tx*8];
            ulonglong2 b23 = *(const ulonglong2*)&Bs[kk][tx*8+4];
            u64 rb2[4] = { b01.x, b01.y, b23.x, b23.y };
            u64 rad[8];
            rad[0] = pkdup(a0.x); rad[1] = pkdup(a0.y);
            rad[2] = pkdup(a0.z); rad[3] = pkdup(a0.w);
            rad[4] = pkdup(a1.x); rad[5] = pkdup(a1.y);
            rad[6] = pkdup(a1.z); rad[7] = pkdup(a1.w);
            #pragma unroll
            for (int i = 0; i < 8; i++)
                #pragma unroll
                for (int jp = 0; jp < 4; jp++)
                    acc2[i][jp] = fma2(rad[i], rb2[jp], acc2[i][jp]);
        }
        __syncthreads();
    }

    float bv[8];
    #pragma unroll
    for (int j = 0; j < 8; j++) bv[j] = bias[bcol + tx*8 + j];
    #pragma unroll
    for (int i = 0; i < 8; i++) {
        float a[8];
        #pragma unroll
        for (int jp = 0; jp < 4; jp++) unpk2(a[2*jp], a[2*jp+1], acc2[i][jp]);
        float* Cp = C + (size_t)(brow + ty*8 + i) * N + bcol + tx*8;
        *(float4*)Cp     = make_float4(a[0]+bv[0], a[1]+bv[1], a[2]+bv[2], a[3]+bv[3]);
        *(float4*)(Cp+4) = make_float4(a[4]+bv[4], a[5]+bv[5], a[6]+bv[6], a[7]+bv[7]);
    }
}

// ---------------------------------------------------------------------------
// Causal flash attention, fp32, f32x2-packed GEMM loops.
// Block = (q-tile of 64 rows, one (b,h)); 256 threads = 16x16; 4x4 tiles.
// ---------------------------------------------------------------------------
#define PQ 68
#define SMEM_FLOATS (4*64*PQ)

__global__ __launch_bounds__(256)
void flash_attn(const float* __restrict__ Qp, const float* __restrict__ Kp,
                const float* __restrict__ Vp, float* __restrict__ Op)
{
    extern __shared__ float sm[];
    float* smQ = sm;
    float* smK = sm + 64*PQ;
    float* smV = sm + 2*64*PQ;
    float* smP = sm + 3*64*PQ;

    const int tid = threadIdx.x;
    const int ty  = tid >> 4;
    const int tx  = tid & 15;
    const int qt  = blockIdx.x;
    const int q0  = qt * 64;
    const int b   = blockIdx.y >> 4;
    const int h   = blockIdx.y & 15;

    const size_t headoff = (size_t)h * DK_;
    const float* Qg = Qp + ((size_t)(b*S_) + q0) * D_ + headoff;

    // Load Q tile transposed into smem, pre-scaled by 1/sqrt(DK)
    for (int i = tid; i < 64*16; i += 256) {
        int r = i >> 4, k4 = (i & 15) << 2;
        float4 v = *(const float4*)(Qg + (size_t)r * D_ + k4);
        smQ[(k4+0)*PQ + r] = v.x * 0.125f;
        smQ[(k4+1)*PQ + r] = v.y * 0.125f;
        smQ[(k4+2)*PQ + r] = v.z * 0.125f;
        smQ[(k4+3)*PQ + r] = v.w * 0.125f;
    }

    float m_i[4], l_i[4];
    u64 o2[4][2];
    #pragma unroll
    for (int i = 0; i < 4; i++) {
        m_i[i] = -INFINITY; l_i[i] = 0.f;
        o2[i][0] = 0ULL; o2[i][1] = 0ULL;
    }

    for (int t = 0; t <= qt; t++) {
        const float* Kg = Kp + ((size_t)(b*S_) + t*64) * D_ + headoff;
        const float* Vg = Vp + ((size_t)(b*S_) + t*64) * D_ + headoff;
        __syncthreads();   // previous iteration done with smK/smV
        for (int i = tid; i < 64*16; i += 256) {
            int r = i >> 4, k4 = (i & 15) << 2;
            float4 kv = *(const float4*)(Kg + (size_t)r * D_ + k4);
            smK[(k4+0)*PQ + r] = kv.x;
            smK[(k4+1)*PQ + r] = kv.y;
            smK[(k4+2)*PQ + r] = kv.z;
            smK[(k4+3)*PQ + r] = kv.w;
            float4 vv = *(const float4*)(Vg + (size_t)r * D_ + k4);
            *(float4*)&smV[r*PQ + k4] = vv;
        }
        __syncthreads();

        // S = (Q*scale) @ K^T  — packed over j-pairs
        u64 s2[4][2];
        #pragma unroll
        for (int i = 0; i < 4; i++) { s2[i][0] = 0ULL; s2[i][1] = 0ULL; }

        #pragma unroll 16
        for (int kk = 0; kk < 64; kk++) {
            float4 rav = *(const float4*)&smQ[kk*PQ + ty*4];
            ulonglong2 rbv = *(const ulonglong2*)&smK[kk*PQ + tx*4];
            u64 rad[4] = { pkdup(rav.x), pkdup(rav.y), pkdup(rav.z), pkdup(rav.w) };
            #pragma unroll
            for (int i = 0; i < 4; i++) {
                s2[i][0] = fma2(rad[i], rbv.x, s2[i][0]);
                s2[i][1] = fma2(rad[i], rbv.y, s2[i][1]);
            }
        }

        float s[4][4];
        #pragma unroll
        for (int i = 0; i < 4; i++) {
            unpk2(s[i][0], s[i][1], s2[i][0]);
            unpk2(s[i][2], s[i][3], s2[i][1]);
        }

        if (t == qt) {  // diagonal tile: mask col > row
            #pragma unroll
            for (int i = 0; i < 4; i++)
                #pragma unroll
                for (int j = 0; j < 4; j++)
                    if (tx*4 + j > ty*4 + i) s[i][j] = -INFINITY;
        }

        // online softmax update (row stats replicated across 16 tx lanes)
        #pragma unroll
        for (int i = 0; i < 4; i++) {
            float rm = fmaxf(fmaxf(s[i][0], s[i][1]), fmaxf(s[i][2], s[i][3]));
            rm = fmaxf(rm, __shfl_xor_sync(0xffffffffu, rm, 1));
            rm = fmaxf(rm, __shfl_xor_sync(0xffffffffu, rm, 2));
            rm = fmaxf(rm, __shfl_xor_sync(0xffffffffu, rm, 4));
            rm = fmaxf(rm, __shfl_xor_sync(0xffffffffu, rm, 8));
            float mnew  = fmaxf(m_i[i], rm);
            float alpha = __expf(m_i[i] - mnew);
            m_i[i] = mnew;
            float rs = 0.f;
            #pragma unroll
            for (int j = 0; j < 4; j++) {
                float p = __expf(s[i][j] - mnew);
                s[i][j] = p; rs += p;
            }
            rs += __shfl_xor_sync(0xffffffffu, rs, 1);
            rs += __shfl_xor_sync(0xffffffffu, rs, 2);
            rs += __shfl_xor_sync(0xffffffffu, rs, 4);
            rs += __shfl_xor_sync(0xffffffffu, rs, 8);
            l_i[i] = l_i[i]*alpha + rs;
            u64 a2 = pkdup(alpha);
            o2[i][0] = mul2(o2[i][0], a2);
            o2[i][1] = mul2(o2[i][1], a2);
            *(float4*)&smP[(ty*4+i)*PQ + tx*4] =
                make_float4(s[i][0], s[i][1], s[i][2], s[i][3]);
        }
        __syncthreads();

        // O += P @ V  — packed over j-pairs
        #pragma unroll 4
        for (int j0 = 0; j0 < 64; j0 += 4) {
            float rp[4][4];
            ulonglong2 rv2[4];
            #pragma unroll
            for (int i = 0; i < 4; i++)
                *(float4*)rp[i] = *(const float4*)&smP[(ty*4+i)*PQ + j0];
            #pragma unroll
            for (int u = 0; u < 4; u++)
                rv2[u] = *(const ulonglong2*)&smV[(j0+u)*PQ + tx*4];
            #pragma unroll
            for (int i = 0; i < 4; i++) {
                #pragma unroll
                for (int u = 0; u < 4; u++) {
                    u64 rpd = pkdup(rp[i][u]);
                    o2[i][0] = fma2(rpd, rv2[u].x, o2[i][0]);
                    o2[i][1] = fma2(rpd, rv2[u].y, o2[i][1]);
                }
            }
        }
    }

    // normalize and store
    float* Og = Op + ((size_t)(b*S_) + q0) * D_ + headoff;
    #pragma unroll
    for (int i = 0; i < 4; i++) {
        float inv = 1.f / l_i[i];
        float o[4];
        unpk2(o[0], o[1], o2[i][0]);
        unpk2(o[2], o[3], o2[i][1]);
        *(float4*)(Og + (size_t)(ty*4+i)*D_ + tx*4) =
            make_float4(o[0]*inv, o[1]*inv, o[2]*inv, o[3]*inv);
    }
}

// ---------------------------------------------------------------------------
extern "C" void kernel_launch(void* const* d_in, const int* in_sizes, int n_in,
                              void* d_out, int out_size)
{
    const float* q  = (const float*)d_in[0];
    const float* k  = (const float*)d_in[1];
    const float* v  = (const float*)d_in[2];
    const float* Wq = (const float*)d_in[3];
    const float* bq = (const float*)d_in[4];
    const float* Wk = (const float*)d_in[5];
    const float* bk = (const float*)d_in[6];
    const float* Wv = (const float*)d_in[7];
    const float* bv = (const float*)d_in[8];
    const float* Wo = (const float*)d_in[9];
    const float* bo = (const float*)d_in[10];
    // d_in[11] = causal_mask: causality computed analytically, not read
    float* out = (float*)d_out;

    float *Qp, *Kp, *Vp, *Op;
    cudaGetSymbolAddress((void**)&Qp, g_Qp);
    cudaGetSymbolAddress((void**)&Kp, g_Kp);
    cudaGetSymbolAddress((void**)&Vp, g_Vp);
    cudaGetSymbolAddress((void**)&Op, g_Op);

    dim3 gg(D_/128, M_/128);
    sgemm_wt_bias<<<gg, 256>>>(q, Wq, bq, Qp);
    sgemm_wt_bias<<<gg, 256>>>(k, Wk, bk, Kp);
    sgemm_wt_bias<<<gg, 256>>>(v, Wv, bv, Vp);

    const int smem = SMEM_FLOATS * (int)sizeof(float);   // 69632 B
    cudaFuncSetAttribute(flash_attn,
                         cudaFuncAttributeMaxDynamicSharedMemorySize, smem);
    flash_attn<<<dim3(S_/64, B_*H_), 256, smem>>>(Qp, Kp, Vp, Op);

    sgemm_wt_bias<<<gg, 256>>>(Op, Wo, bo, out);
}

// round 8
// speedup vs baseline: 1.4999x; 1.4668x over previous
#include <cuda_runtime.h>
#include <cuda_bf16.h>
#include <math.h>
#include <stdint.h>

#define B_  4
#define S_  2048
#define D_  1024
#define H_  16
#define DK_ 64
#define M_  (B_*S_)   // 8192

typedef unsigned long long u64;
typedef unsigned int u32;

// ===================== warp-level tensor-core helpers (non-"a" ISA) ========
__device__ __forceinline__ u32 smem_to_u32(const void* p) {
    u32 a;
    asm("{ .reg .u64 t; cvta.to.shared.u64 t, %1; cvt.u32.u64 %0, t; }"
        : "=r"(a) : "l"(p));
    return a;
}
__device__ __forceinline__ void ldsm4(u32& r0, u32& r1, u32& r2, u32& r3, u32 a) {
    asm volatile("ldmatrix.sync.aligned.m8n8.x4.shared.b16 {%0,%1,%2,%3}, [%4];"
                 : "=r"(r0), "=r"(r1), "=r"(r2), "=r"(r3) : "r"(a));
}
__device__ __forceinline__ void mma16816(float* c, const u32* a, u32 b0, u32 b1) {
    asm volatile("mma.sync.aligned.m16n8k16.row.col.f32.bf16.bf16.f32 "
                 "{%0,%1,%2,%3}, {%4,%5,%6,%7}, {%8,%9}, {%0,%1,%2,%3};"
                 : "+f"(c[0]), "+f"(c[1]), "+f"(c[2]), "+f"(c[3])
                 : "r"(a[0]), "r"(a[1]), "r"(a[2]), "r"(a[3]), "r"(b0), "r"(b1));
}

// ===================== fp32x2 helpers (flash attention) ====================
__device__ __forceinline__ u64 pk2(float lo, float hi) {
    u64 r; asm("mov.b64 %0, {%1, %2};" : "=l"(r) : "f"(lo), "f"(hi)); return r;
}
__device__ __forceinline__ u64 pkdup(float v) { return pk2(v, v); }
__device__ __forceinline__ void unpk2(float& lo, float& hi, u64 v) {
    asm("mov.b64 {%0, %1}, %2;" : "=f"(lo), "=f"(hi) : "l"(v));
}
__device__ __forceinline__ u64 fma2(u64 a, u64 b, u64 c) {
    u64 d; asm("fma.rn.f32x2 %0, %1, %2, %3;" : "=l"(d) : "l"(a), "l"(b), "l"(c)); return d;
}
__device__ __forceinline__ u64 mul2(u64 a, u64 b) {
    u64 d; asm("mul.rn.f32x2 %0, %1, %2;" : "=l"(d) : "l"(a), "l"(b)); return d;
}

// ---------------- scratch (device globals: allocation-free) ----------------
__device__ float g_Qp[M_*D_];
__device__ float g_Kp[M_*D_];
__device__ float g_Vp[M_*D_];
__device__ float g_Op[M_*D_];
__device__ __nv_bfloat16 g_xh[M_*D_];
__device__ __nv_bfloat16 g_xl[M_*D_];
__device__ __nv_bfloat16 g_wh[D_*D_];
__device__ __nv_bfloat16 g_wl[D_*D_];

// ---------------------------------------------------------------------------
// split fp32 -> bf16 hi + bf16 lo   (x = hi + lo, ~17 mantissa bits)
// ---------------------------------------------------------------------------
__global__ __launch_bounds__(256)
void cvt_split(const float* __restrict__ x, __nv_bfloat16* __restrict__ h,
               __nv_bfloat16* __restrict__ l, int n4)
{
    int i = blockIdx.x * 256 + threadIdx.x;
    if (i >= n4) return;
    float4 v = ((const float4*)x)[i];
    __nv_bfloat16 h0 = __float2bfloat16(v.x), h1 = __float2bfloat16(v.y);
    __nv_bfloat16 h2 = __float2bfloat16(v.z), h3 = __float2bfloat16(v.w);
    __nv_bfloat16 l0 = __float2bfloat16(v.x - __bfloat162float(h0));
    __nv_bfloat16 l1 = __float2bfloat16(v.y - __bfloat162float(h1));
    __nv_bfloat16 l2 = __float2bfloat16(v.z - __bfloat162float(h2));
    __nv_bfloat16 l3 = __float2bfloat16(v.w - __bfloat162float(h3));
    ((__nv_bfloat162*)h)[2*i+0] = __nv_bfloat162(h0, h1);
    ((__nv_bfloat162*)h)[2*i+1] = __nv_bfloat162(h2, h3);
    ((__nv_bfloat162*)l)[2*i+0] = __nv_bfloat162(l0, l1);
    ((__nv_bfloat162*)l)[2*i+1] = __nv_bfloat162(l2, l3);
}

// ---------------------------------------------------------------------------
// mma.sync bf16x3 GEMM:  C[M,N] = (Ah+Al)[M,K] @ (Bh+Bl)[N,K]^T + bias[N]
// CTA 128x128, K-chunk 64, 8 warps (warp tile 64x32), m16n8k16 HMMA,
// fp32 register accumulators. SW128 xor-swizzled smem, conflict-free ldmatrix.
// ---------------------------------------------------------------------------
#define GEMM_SMEM (4*16384)   // Ah, Al, Bh, Bl tiles: 128 x 64 bf16 each

__global__ __launch_bounds__(256)
void gemm_mma(const __nv_bfloat16* __restrict__ Ah, const __nv_bfloat16* __restrict__ Al,
              const __nv_bfloat16* __restrict__ Bh, const __nv_bfloat16* __restrict__ Bl,
              const float* __restrict__ bias, float* __restrict__ C)
{
    extern __shared__ char smc[];
    const u32 sb   = smem_to_u32(smc);
    const int tid  = threadIdx.x, wid = tid >> 5, lane = tid & 31;
    const int brow = blockIdx.y * 128, bcol = blockIdx.x * 128;
    const int wm   = wid & 1;        // 0/1 -> 64-row half
    const int wn   = wid >> 1;       // 0..3 -> 32-col quarter
    const int lr   = lane & 15, lhi = lane >> 4;

    float acc[4][4][4];
    #pragma unroll
    for (int mt = 0; mt < 4; mt++)
        #pragma unroll
        for (int nt = 0; nt < 4; nt++)
            #pragma unroll
            for (int r = 0; r < 4; r++) acc[mt][nt][r] = 0.f;

    const __nv_bfloat16* gsrc[4] = { Ah, Al, Bh, Bl };

    for (int c = 0; c < 16; c++) {
        const int k0 = c * 64;
        // fill 4 tiles: 128 rows x 64 bf16 (128B/row), SW128 xor-swizzled
        #pragma unroll
        for (int t2 = 0; t2 < 4; t2++) {
            const __nv_bfloat16* g = gsrc[t2];
            const int rowbase = (t2 < 2) ? brow : bcol;
            char* sm = smc + t2 * 16384;
            #pragma unroll
            for (int seg = tid; seg < 1024; seg += 256) {
                int r = seg >> 3, s = seg & 7;
                uint4 v = *(const uint4*)(g + (size_t)(rowbase + r) * D_ + k0 + s*8);
                u32 off = r*128 + s*16;
                *(uint4*)(sm + (off ^ ((off >> 3) & 0x70))) = v;
            }
        }
        __syncthreads();

        #pragma unroll
        for (int ks = 0; ks < 4; ks++) {
            // A fragments (hi+lo) for the warp's 4 m-tiles
            u32 ah[4][4], al[4][4];
            #pragma unroll
            for (int mt = 0; mt < 4; mt++) {
                int r = wm*64 + mt*16 + lr;
                u32 off = (u32)(r*128 + (ks*2 + lhi)*16);
                off ^= (off >> 3) & 0x70;
                ldsm4(ah[mt][0], ah[mt][1], ah[mt][2], ah[mt][3], sb + off);
                ldsm4(al[mt][0], al[mt][1], al[mt][2], al[mt][3], sb + 16384 + off);
            }
            // B fragments: one x4 covers two n-tiles
            #pragma unroll
            for (int np = 0; np < 2; np++) {
                int r = wn*32 + np*16 + lr;
                u32 off = (u32)(r*128 + (ks*2 + lhi)*16);
                off ^= (off >> 3) & 0x70;
                u32 bh[4], bl[4];
                ldsm4(bh[0], bh[1], bh[2], bh[3], sb + 2*16384 + off);
                ldsm4(bl[0], bl[1], bl[2], bl[3], sb + 3*16384 + off);
                #pragma unroll
                for (int half = 0; half < 2; half++) {
                    const int nt = np*2 + half;
                    const u32 fh0 = bh[half], fh1 = bh[half+2];
                    const u32 fl0 = bl[half], fl1 = bl[half+2];
                    #pragma unroll
                    for (int mt = 0; mt < 4; mt++) {
                        mma16816(acc[mt][nt], ah[mt], fh0, fh1);
                        mma16816(acc[mt][nt], al[mt], fh0, fh1);
                        mma16816(acc[mt][nt], ah[mt], fl0, fl1);
                    }
                }
            }
        }
        __syncthreads();
    }

    // epilogue: bias add + direct float2 stores
    const int r0 = lane >> 2, c0 = (lane & 3) * 2;
    #pragma unroll
    for (int nt = 0; nt < 4; nt++) {
        const int col = bcol + wn*32 + nt*8 + c0;
        float2 bv = *(const float2*)&bias[col];
        #pragma unroll
        for (int mt = 0; mt < 4; mt++) {
            const int row = brow + wm*64 + mt*16 + r0;
            float2 v0 = make_float2(acc[mt][nt][0] + bv.x, acc[mt][nt][1] + bv.y);
            float2 v1 = make_float2(acc[mt][nt][2] + bv.x, acc[mt][nt][3] + bv.y);
            *(float2*)(C + (size_t)row       * D_ + col) = v0;
            *(float2*)(C + (size_t)(row + 8) * D_ + col) = v1;
        }
    }
}

// ---------------------------------------------------------------------------
// Causal flash attention, fp32, f32x2-packed GEMM loops (unchanged).
// ---------------------------------------------------------------------------
#define PQ 68
#define SMEM_FLOATS (4*64*PQ)

__global__ __launch_bounds__(256)
void flash_attn(const float* __restrict__ Qp, const float* __restrict__ Kp,
                const float* __restrict__ Vp, float* __restrict__ Op)
{
    extern __shared__ float sm[];
    float* smQ = sm;
    float* smK = sm + 64*PQ;
    float* smV = sm + 2*64*PQ;
    float* smP = sm + 3*64*PQ;

    const int tid = threadIdx.x;
    const int ty  = tid >> 4;
    const int tx  = tid & 15;
    const int qt  = blockIdx.x;
    const int q0  = qt * 64;
    const int b   = blockIdx.y >> 4;
    const int h   = blockIdx.y & 15;

    const size_t headoff = (size_t)h * DK_;
    const float* Qg = Qp + ((size_t)(b*S_) + q0) * D_ + headoff;

    for (int i = tid; i < 64*16; i += 256) {
        int r = i >> 4, k4 = (i & 15) << 2;
        float4 v = *(const float4*)(Qg + (size_t)r * D_ + k4);
        smQ[(k4+0)*PQ + r] = v.x * 0.125f;
        smQ[(k4+1)*PQ + r] = v.y * 0.125f;
        smQ[(k4+2)*PQ + r] = v.z * 0.125f;
        smQ[(k4+3)*PQ + r] = v.w * 0.125f;
    }

    float m_i[4], l_i[4];
    u64 o2[4][2];
    #pragma unroll
    for (int i = 0; i < 4; i++) {
        m_i[i] = -INFINITY; l_i[i] = 0.f;
        o2[i][0] = 0ULL; o2[i][1] = 0ULL;
    }

    for (int t = 0; t <= qt; t++) {
        const float* Kg = Kp + ((size_t)(b*S_) + t*64) * D_ + headoff;
        const float* Vg = Vp + ((size_t)(b*S_) + t*64) * D_ + headoff;
        __syncthreads();
        for (int i = tid; i < 64*16; i += 256) {
            int r = i >> 4, k4 = (i & 15) << 2;
            float4 kv = *(const float4*)(Kg + (size_t)r * D_ + k4);
            smK[(k4+0)*PQ + r] = kv.x;
            smK[(k4+1)*PQ + r] = kv.y;
            smK[(k4+2)*PQ + r] = kv.z;
            smK[(k4+3)*PQ + r] = kv.w;
            float4 vv = *(const float4*)(Vg + (size_t)r * D_ + k4);
            *(float4*)&smV[r*PQ + k4] = vv;
        }
        __syncthreads();

        u64 s2[4][2];
        #pragma unroll
        for (int i = 0; i < 4; i++) { s2[i][0] = 0ULL; s2[i][1] = 0ULL; }

        #pragma unroll 16
        for (int kk = 0; kk < 64; kk++) {
            float4 rav = *(const float4*)&smQ[kk*PQ + ty*4];
            ulonglong2 rbv = *(const ulonglong2*)&smK[kk*PQ + tx*4];
            u64 rad[4] = { pkdup(rav.x), pkdup(rav.y), pkdup(rav.z), pkdup(rav.w) };
            #pragma unroll
            for (int i = 0; i < 4; i++) {
                s2[i][0] = fma2(rad[i], rbv.x, s2[i][0]);
                s2[i][1] = fma2(rad[i], rbv.y, s2[i][1]);
            }
        }

        float s[4][4];
        #pragma unroll
        for (int i = 0; i < 4; i++) {
            unpk2(s[i][0], s[i][1], s2[i][0]);
            unpk2(s[i][2], s[i][3], s2[i][1]);
        }

        if (t == qt) {
            #pragma unroll
            for (int i = 0; i < 4; i++)
                #pragma unroll
                for (int j = 0; j < 4; j++)
                    if (tx*4 + j > ty*4 + i) s[i][j] = -INFINITY;
        }

        #pragma unroll
        for (int i = 0; i < 4; i++) {
            float rm = fmaxf(fmaxf(s[i][0], s[i][1]), fmaxf(s[i][2], s[i][3]));
            rm = fmaxf(rm, __shfl_xor_sync(0xffffffffu, rm, 1));
            rm = fmaxf(rm, __shfl_xor_sync(0xffffffffu, rm, 2));
            rm = fmaxf(rm, __shfl_xor_sync(0xffffffffu, rm, 4));
            rm = fmaxf(rm, __shfl_xor_sync(0xffffffffu, rm, 8));
            float mnew  = fmaxf(m_i[i], rm);
            float alpha = __expf(m_i[i] - mnew);
            m_i[i] = mnew;
            float rs = 0.f;
            #pragma unroll
            for (int j = 0; j < 4; j++) {
                float p = __expf(s[i][j] - mnew);
                s[i][j] = p; rs += p;
            }
            rs += __shfl_xor_sync(0xffffffffu, rs, 1);
            rs += __shfl_xor_sync(0xffffffffu, rs, 2);
            rs += __shfl_xor_sync(0xffffffffu, rs, 4);
            rs += __shfl_xor_sync(0xffffffffu, rs, 8);
            l_i[i] = l_i[i]*alpha + rs;
            u64 a2 = pkdup(alpha);
            o2[i][0] = mul2(o2[i][0], a2);
            o2[i][1] = mul2(o2[i][1], a2);
            *(float4*)&smP[(ty*4+i)*PQ + tx*4] =
                make_float4(s[i][0], s[i][1], s[i][2], s[i][3]);
        }
        __syncthreads();

        #pragma unroll 4
        for (int j0 = 0; j0 < 64; j0 += 4) {
            float rp[4][4];
            ulonglong2 rv2[4];
            #pragma unroll
            for (int i = 0; i < 4; i++)
                *(float4*)rp[i] = *(const float4*)&smP[(ty*4+i)*PQ + j0];
            #pragma unroll
            for (int u = 0; u < 4; u++)
                rv2[u] = *(const ulonglong2*)&smV[(j0+u)*PQ + tx*4];
            #pragma unroll
            for (int i = 0; i < 4; i++) {
                #pragma unroll
                for (int u = 0; u < 4; u++) {
                    u64 rpd = pkdup(rp[i][u]);
                    o2[i][0] = fma2(rpd, rv2[u].x, o2[i][0]);
                    o2[i][1] = fma2(rpd, rv2[u].y, o2[i][1]);
                }
            }
        }
    }

    float* Og = Op + ((size_t)(b*S_) + q0) * D_ + headoff;
    #pragma unroll
    for (int i = 0; i < 4; i++) {
        float inv = 1.f / l_i[i];
        float o[4];
        unpk2(o[0], o[1], o2[i][0]);
        unpk2(o[2], o[3], o2[i][1]);
        *(float4*)(Og + (size_t)(ty*4+i)*D_ + tx*4) =
            make_float4(o[0]*inv, o[1]*inv, o[2]*inv, o[3]*inv);
    }
}

// ---------------------------------------------------------------------------
extern "C" void kernel_launch(void* const* d_in, const int* in_sizes, int n_in,
                              void* d_out, int out_size)
{
    const float* q  = (const float*)d_in[0];
    const float* k  = (const float*)d_in[1];
    const float* v  = (const float*)d_in[2];
    const float* Wq = (const float*)d_in[3];
    const float* bq = (const float*)d_in[4];
    const float* Wk = (const float*)d_in[5];
    const float* bk = (const float*)d_in[6];
    const float* Wv = (const float*)d_in[7];
    const float* bv = (const float*)d_in[8];
    const float* Wo = (const float*)d_in[9];
    const float* bo = (const float*)d_in[10];
    float* out = (float*)d_out;

    float *Qp, *Kp, *Vp, *Op;
    __nv_bfloat16 *xh, *xl, *wh, *wl;
    cudaGetSymbolAddress((void**)&Qp, g_Qp);
    cudaGetSymbolAddress((void**)&Kp, g_Kp);
    cudaGetSymbolAddress((void**)&Vp, g_Vp);
    cudaGetSymbolAddress((void**)&Op, g_Op);
    cudaGetSymbolAddress((void**)&xh, g_xh);
    cudaGetSymbolAddress((void**)&xl, g_xl);
    cudaGetSymbolAddress((void**)&wh, g_wh);
    cudaGetSymbolAddress((void**)&wl, g_wl);

    cudaFuncSetAttribute(gemm_mma,
                         cudaFuncAttributeMaxDynamicSharedMemorySize, GEMM_SMEM);

    const int nx4 = M_*D_/4, nw4 = D_*D_/4;
    dim3 gg(D_/128, M_/128);

    // Q projection
    cvt_split<<<nx4/256, 256>>>(q, xh, xl, nx4);
    cvt_split<<<nw4/256, 256>>>(Wq, wh, wl, nw4);
    gemm_mma<<<gg, 256, GEMM_SMEM>>>(xh, xl, wh, wl, bq, Qp);
    // K projection
    cvt_split<<<nx4/256, 256>>>(k, xh, xl, nx4);
    cvt_split<<<nw4/256, 256>>>(Wk, wh, wl, nw4);
    gemm_mma<<<gg, 256, GEMM_SMEM>>>(xh, xl, wh, wl, bk, Kp);
    // V projection
    cvt_split<<<nx4/256, 256>>>(v, xh, xl, nx4);
    cvt_split<<<nw4/256, 256>>>(Wv, wh, wl, nw4);
    gemm_mma<<<gg, 256, GEMM_SMEM>>>(xh, xl, wh, wl, bv, Vp);

    // attention
    const int smem = SMEM_FLOATS * (int)sizeof(float);
    cudaFuncSetAttribute(flash_attn,
                         cudaFuncAttributeMaxDynamicSharedMemorySize, smem);
    flash_attn<<<dim3(S_/64, B_*H_), 256, smem>>>(Qp, Kp, Vp, Op);

    // output projection
    cvt_split<<<nx4/256, 256>>>(Op, xh, xl, nx4);
    cvt_split<<<nw4/256, 256>>>(Wo, wh, wl, nw4);
    gemm_mma<<<gg, 256, GEMM_SMEM>>>(xh, xl, wh, wl, bo, out);
}

// round 10
// speedup vs baseline: 1.5413x; 1.0276x over previous
#include <cuda_runtime.h>
#include <cuda_bf16.h>
#include <math.h>
#include <stdint.h>

#define B_  4
#define S_  2048
#define D_  1024
#define H_  16
#define DK_ 64
#define M_  (B_*S_)   // 8192

typedef unsigned long long u64;
typedef unsigned int u32;

// ===================== warp-level tensor-core helpers (non-"a" ISA) ========
__device__ __forceinline__ u32 smem_to_u32(const void* p) {
    u32 a;
    asm("{ .reg .u64 t; cvta.to.shared.u64 t, %1; cvt.u32.u64 %0, t; }"
        : "=r"(a) : "l"(p));
    return a;
}
__device__ __forceinline__ void ldsm4(u32& r0, u32& r1, u32& r2, u32& r3, u32 a) {
    asm volatile("ldmatrix.sync.aligned.m8n8.x4.shared.b16 {%0,%1,%2,%3}, [%4];"
                 : "=r"(r0), "=r"(r1), "=r"(r2), "=r"(r3) : "r"(a));
}
__device__ __forceinline__ void ldsm4t(u32& r0, u32& r1, u32& r2, u32& r3, u32 a) {
    asm volatile("ldmatrix.sync.aligned.m8n8.x4.trans.shared.b16 {%0,%1,%2,%3}, [%4];"
                 : "=r"(r0), "=r"(r1), "=r"(r2), "=r"(r3) : "r"(a));
}
__device__ __forceinline__ void mma16816(float* c, const u32* a, u32 b0, u32 b1) {
    asm volatile("mma.sync.aligned.m16n8k16.row.col.f32.bf16.bf16.f32 "
                 "{%0,%1,%2,%3}, {%4,%5,%6,%7}, {%8,%9}, {%0,%1,%2,%3};"
                 : "+f"(c[0]), "+f"(c[1]), "+f"(c[2]), "+f"(c[3])
                 : "r"(a[0]), "r"(a[1]), "r"(a[2]), "r"(a[3]), "r"(b0), "r"(b1));
}
// pack (hi, lo) floats -> bf16x2 register (low half = lo)
__device__ __forceinline__ u32 pkbf(float hi, float lo) {
    u32 d;
    asm("cvt.rn.bf16x2.f32 %0, %1, %2;" : "=r"(d) : "f"(hi), "f"(lo));
    return d;
}
__device__ __forceinline__ float bf_lo(u32 v) { return __int_as_float((int)(v << 16)); }
__device__ __forceinline__ float bf_hi(u32 v) { return __int_as_float((int)(v & 0xffff0000u)); }

// ---------------- scratch (device globals: allocation-free) ----------------
__device__ float g_Qp[M_*D_];
__device__ float g_Kp[M_*D_];
__device__ float g_Vp[M_*D_];
__device__ float g_Op[M_*D_];
__device__ __nv_bfloat16 g_xh[M_*D_];
__device__ __nv_bfloat16 g_xl[M_*D_];
__device__ __nv_bfloat16 g_wh[D_*D_];
__device__ __nv_bfloat16 g_wl[D_*D_];
__device__ __nv_bfloat16 g_qh[M_*D_];
__device__ __nv_bfloat16 g_ql[M_*D_];
__device__ __nv_bfloat16 g_kh[M_*D_];
__device__ __nv_bfloat16 g_kl[M_*D_];
__device__ __nv_bfloat16 g_vh[M_*D_];
__device__ __nv_bfloat16 g_vl[M_*D_];

// ---------------------------------------------------------------------------
// split fp32 -> bf16 hi + bf16 lo   (x = hi + lo, ~17 mantissa bits)
// ---------------------------------------------------------------------------
__global__ __launch_bounds__(256)
void cvt_split(const float* __restrict__ x, __nv_bfloat16* __restrict__ h,
               __nv_bfloat16* __restrict__ l, int n4)
{
    int i = blockIdx.x * 256 + threadIdx.x;
    if (i >= n4) return;
    float4 v = ((const float4*)x)[i];
    __nv_bfloat16 h0 = __float2bfloat16(v.x), h1 = __float2bfloat16(v.y);
    __nv_bfloat16 h2 = __float2bfloat16(v.z), h3 = __float2bfloat16(v.w);
    __nv_bfloat16 l0 = __float2bfloat16(v.x - __bfloat162float(h0));
    __nv_bfloat16 l1 = __float2bfloat16(v.y - __bfloat162float(h1));
    __nv_bfloat16 l2 = __float2bfloat16(v.z - __bfloat162float(h2));
    __nv_bfloat16 l3 = __float2bfloat16(v.w - __bfloat162float(h3));
    ((__nv_bfloat162*)h)[2*i+0] = __nv_bfloat162(h0, h1);
    ((__nv_bfloat162*)h)[2*i+1] = __nv_bfloat162(h2, h3);
    ((__nv_bfloat162*)l)[2*i+0] = __nv_bfloat162(l0, l1);
    ((__nv_bfloat162*)l)[2*i+1] = __nv_bfloat162(l2, l3);
}

// ---------------------------------------------------------------------------
// mma.sync bf16x3 GEMM:  C[M,N] = (Ah+Al)[M,K] @ (Bh+Bl)[N,K]^T + bias[N]
// ---------------------------------------------------------------------------
#define GEMM_SMEM (4*16384)

__global__ __launch_bounds__(256)
void gemm_mma(const __nv_bfloat16* __restrict__ Ah, const __nv_bfloat16* __restrict__ Al,
              const __nv_bfloat16* __restrict__ Bh, const __nv_bfloat16* __restrict__ Bl,
              const float* __restrict__ bias, float* __restrict__ C)
{
    extern __shared__ char smc[];
    const u32 sb   = smem_to_u32(smc);
    const int tid  = threadIdx.x, wid = tid >> 5, lane = tid & 31;
    const int brow = blockIdx.y * 128, bcol = blockIdx.x * 128;
    const int wm   = wid & 1;
    const int wn   = wid >> 1;
    const int lr   = lane & 15, lhi = lane >> 4;

    float acc[4][4][4];
    #pragma unroll
    for (int mt = 0; mt < 4; mt++)
        #pragma unroll
        for (int nt = 0; nt < 4; nt++)
            #pragma unroll
            for (int r = 0; r < 4; r++) acc[mt][nt][r] = 0.f;

    const __nv_bfloat16* gsrc[4] = { Ah, Al, Bh, Bl };

    for (int c = 0; c < 16; c++) {
        const int k0 = c * 64;
        #pragma unroll
        for (int t2 = 0; t2 < 4; t2++) {
            const __nv_bfloat16* g = gsrc[t2];
            const int rowbase = (t2 < 2) ? brow : bcol;
            char* sm = smc + t2 * 16384;
            #pragma unroll
            for (int seg = tid; seg < 1024; seg += 256) {
                int r = seg >> 3, s = seg & 7;
                uint4 v = *(const uint4*)(g + (size_t)(rowbase + r) * D_ + k0 + s*8);
                u32 off = r*128 + s*16;
                *(uint4*)(sm + (off ^ ((off >> 3) & 0x70))) = v;
            }
        }
        __syncthreads();

        #pragma unroll
        for (int ks = 0; ks < 4; ks++) {
            u32 ah[4][4], al[4][4];
            #pragma unroll
            for (int mt = 0; mt < 4; mt++) {
                int r = wm*64 + mt*16 + lr;
                u32 off = (u32)(r*128 + (ks*2 + lhi)*16);
                off ^= (off >> 3) & 0x70;
                ldsm4(ah[mt][0], ah[mt][1], ah[mt][2], ah[mt][3], sb + off);
                ldsm4(al[mt][0], al[mt][1], al[mt][2], al[mt][3], sb + 16384 + off);
            }
            #pragma unroll
            for (int np = 0; np < 2; np++) {
                int r = wn*32 + np*16 + lr;
                u32 off = (u32)(r*128 + (ks*2 + lhi)*16);
                off ^= (off >> 3) & 0x70;
                u32 bh[4], bl[4];
                ldsm4(bh[0], bh[1], bh[2], bh[3], sb + 2*16384 + off);
                ldsm4(bl[0], bl[1], bl[2], bl[3], sb + 3*16384 + off);
                #pragma unroll
                for (int half = 0; half < 2; half++) {
                    const int nt = np*2 + half;
                    const u32 fh0 = bh[half], fh1 = bh[half+2];
                    const u32 fl0 = bl[half], fl1 = bl[half+2];
                    #pragma unroll
                    for (int mt = 0; mt < 4; mt++) {
                        mma16816(acc[mt][nt], ah[mt], fh0, fh1);
                        mma16816(acc[mt][nt], al[mt], fh0, fh1);
                        mma16816(acc[mt][nt], ah[mt], fl0, fl1);
                    }
                }
            }
        }
        __syncthreads();
    }

    const int r0 = lane >> 2, c0 = (lane & 3) * 2;
    #pragma unroll
    for (int nt = 0; nt < 4; nt++) {
        const int col = bcol + wn*32 + nt*8 + c0;
        float2 bv = *(const float2*)&bias[col];
        #pragma unroll
        for (int mt = 0; mt < 4; mt++) {
            const int row = brow + wm*64 + mt*16 + r0;
            float2 v0 = make_float2(acc[mt][nt][0] + bv.x, acc[mt][nt][1] + bv.y);
            float2 v1 = make_float2(acc[mt][nt][2] + bv.x, acc[mt][nt][3] + bv.y);
            *(float2*)(C + (size_t)row       * D_ + col) = v0;
            *(float2*)(C + (size_t)(row + 8) * D_ + col) = v1;
        }
    }
}

// ---------------------------------------------------------------------------
// Causal flash attention on tensor cores, bf16x3 splits, fp32 softmax/accum.
// Block = (b,h) x 64 q-rows, 4 warps (16 q-rows each). K/V tiles 64x64.
// P stays in registers (S-frag -> A-frag repack), V via ldmatrix.trans.
// ---------------------------------------------------------------------------
#define FA_SMEM (6*8192)

__global__ __launch_bounds__(128)
void flash_attn_mma(const __nv_bfloat16* __restrict__ qh, const __nv_bfloat16* __restrict__ ql,
                    const __nv_bfloat16* __restrict__ kh, const __nv_bfloat16* __restrict__ kl,
                    const __nv_bfloat16* __restrict__ vh, const __nv_bfloat16* __restrict__ vl,
                    float* __restrict__ Op)
{
    extern __shared__ char smf[];
    const u32 sb = smem_to_u32(smf);
    const int tid = threadIdx.x, w = tid >> 5, lane = tid & 31;
    const int qt = blockIdx.x, q0 = qt * 64;
    const int b = blockIdx.y >> 4, h = blockIdx.y & 15;
    const size_t rowbase = (size_t)b * S_;
    const size_t colbase = (size_t)h * 64;

    const int lr = lane & 15, lhi = lane >> 4;
    const int r0 = lane >> 2, cq = (lane & 3) * 2;
    const int rg = w*16 + r0;    // row within the 64-row q tile

    // load Q hi/lo tiles once (64 rows x 64 bf16, SW128 swizzle)
    {
        const __nv_bfloat16* gh = qh + (rowbase + q0) * D_ + colbase;
        const __nv_bfloat16* gl = ql + (rowbase + q0) * D_ + colbase;
        #pragma unroll
        for (int seg = tid; seg < 512; seg += 128) {
            int r = seg >> 3, c = seg & 7;
            u32 off = (u32)(r*128 + c*16); off ^= (off >> 3) & 0x70;
            *(uint4*)(smf + off)        = *(const uint4*)(gh + (size_t)r * D_ + c*8);
            *(uint4*)(smf + 8192 + off) = *(const uint4*)(gl + (size_t)r * D_ + c*8);
        }
    }

    float m0 = -INFINITY, m1 = -INFINITY, l0 = 0.f, l1 = 0.f;
    float o[8][4];
    #pragma unroll
    for (int nt = 0; nt < 8; nt++)
        #pragma unroll
        for (int r = 0; r < 4; r++) o[nt][r] = 0.f;

    for (int t = 0; t <= qt; t++) {
        __syncthreads();
        {
            const size_t base = (rowbase + t*64) * D_ + colbase;
            #pragma unroll
            for (int seg = tid; seg < 512; seg += 128) {
                int r = seg >> 3, c = seg & 7;
                u32 off = (u32)(r*128 + c*16); off ^= (off >> 3) & 0x70;
                size_t g = base + (size_t)r * D_ + c*8;
                *(uint4*)(smf + 2*8192 + off) = *(const uint4*)(kh + g);
                *(uint4*)(smf + 3*8192 + off) = *(const uint4*)(kl + g);
                *(uint4*)(smf + 4*8192 + off) = *(const uint4*)(vh + g);
                *(uint4*)(smf + 5*8192 + off) = *(const uint4*)(vl + g);
            }
        }
        __syncthreads();

        // ---- S = Q K^T (raw, unscaled) ----
        float s[8][4];
        #pragma unroll
        for (int nt = 0; nt < 8; nt++)
            #pragma unroll
            for (int r = 0; r < 4; r++) s[nt][r] = 0.f;

        #pragma unroll
        for (int ks = 0; ks < 4; ks++) {
            u32 offA = (u32)((w*16 + lr)*128 + (ks*2 + lhi)*16);
            offA ^= (offA >> 3) & 0x70;
            u32 aqh[4], aql[4];
            ldsm4(aqh[0], aqh[1], aqh[2], aqh[3], sb + offA);
            ldsm4(aql[0], aql[1], aql[2], aql[3], sb + 8192 + offA);
            #pragma unroll
            for (int np = 0; np < 4; np++) {
                u32 offB = (u32)((np*16 + lr)*128 + (ks*2 + lhi)*16);
                offB ^= (offB >> 3) & 0x70;
                u32 bh[4], bl[4];
                ldsm4(bh[0], bh[1], bh[2], bh[3], sb + 2*8192 + offB);
                ldsm4(bl[0], bl[1], bl[2], bl[3], sb + 3*8192 + offB);
                #pragma unroll
                for (int half = 0; half < 2; half++) {
                    const int nt = np*2 + half;
                    const u32 f0 = bh[half], f1 = bh[half+2];
                    mma16816(s[nt], aqh, f0, f1);
                    mma16816(s[nt], aql, f0, f1);
                    mma16816(s[nt], aqh, bl[half], bl[half+2]);
                }
            }
        }

        // ---- diagonal mask (col cc vs GLOBAL in-tile row rg / rg+8) ----
        if (t == qt) {
            #pragma unroll
            for (int nt = 0; nt < 8; nt++) {
                const int cc = nt*8 + cq;
                if (cc     > rg)     s[nt][0] = -INFINITY;
                if (cc + 1 > rg)     s[nt][1] = -INFINITY;
                if (cc     > rg + 8) s[nt][2] = -INFINITY;
                if (cc + 1 > rg + 8) s[nt][3] = -INFINITY;
            }
        }

        // ---- online softmax (scale 1/8 folded into exp args) ----
        float rm0 = -INFINITY, rm1 = -INFINITY;
        #pragma unroll
        for (int nt = 0; nt < 8; nt++) {
            rm0 = fmaxf(rm0, fmaxf(s[nt][0], s[nt][1]));
            rm1 = fmaxf(rm1, fmaxf(s[nt][2], s[nt][3]));
        }
        rm0 = fmaxf(rm0, __shfl_xor_sync(0xffffffffu, rm0, 1));
        rm0 = fmaxf(rm0, __shfl_xor_sync(0xffffffffu, rm0, 2));
        rm1 = fmaxf(rm1, __shfl_xor_sync(0xffffffffu, rm1, 1));
        rm1 = fmaxf(rm1, __shfl_xor_sync(0xffffffffu, rm1, 2));
        float mn0 = fmaxf(m0, rm0), mn1 = fmaxf(m1, rm1);
        float alpha0 = __expf(0.125f * (m0 - mn0));
        float alpha1 = __expf(0.125f * (m1 - mn1));
        m0 = mn0; m1 = mn1;
        const float m08 = mn0 * 0.125f, m18 = mn1 * 0.125f;
        float rs0 = 0.f, rs1 = 0.f;
        #pragma unroll
        for (int nt = 0; nt < 8; nt++) {
            s[nt][0] = __expf(fmaf(s[nt][0], 0.125f, -m08));
            s[nt][1] = __expf(fmaf(s[nt][1], 0.125f, -m08));
            s[nt][2] = __expf(fmaf(s[nt][2], 0.125f, -m18));
            s[nt][3] = __expf(fmaf(s[nt][3], 0.125f, -m18));
            rs0 += s[nt][0] + s[nt][1];
            rs1 += s[nt][2] + s[nt][3];
        }
        rs0 += __shfl_xor_sync(0xffffffffu, rs0, 1);
        rs0 += __shfl_xor_sync(0xffffffffu, rs0, 2);
        rs1 += __shfl_xor_sync(0xffffffffu, rs1, 1);
        rs1 += __shfl_xor_sync(0xffffffffu, rs1, 2);
        l0 = l0 * alpha0 + rs0;
        l1 = l1 * alpha1 + rs1;
        #pragma unroll
        for (int nt = 0; nt < 8; nt++) {
            o[nt][0] *= alpha0; o[nt][1] *= alpha0;
            o[nt][2] *= alpha1; o[nt][3] *= alpha1;
        }

        // ---- O += P V  (P split hi/lo from registers, V via ldmatrix.trans) ----
        #pragma unroll
        for (int kt = 0; kt < 4; kt++) {
            u32 aph[4], apl[4];
            #pragma unroll
            for (int half = 0; half < 2; half++) {
                const float plo0 = s[2*kt + half][0], phi0 = s[2*kt + half][1];
                const float plo1 = s[2*kt + half][2], phi1 = s[2*kt + half][3];
                u32 h0 = pkbf(phi0, plo0);
                u32 h1 = pkbf(phi1, plo1);
                aph[0 + 2*half] = h0;
                aph[1 + 2*half] = h1;
                apl[0 + 2*half] = pkbf(phi0 - bf_hi(h0), plo0 - bf_lo(h0));
                apl[1 + 2*half] = pkbf(phi1 - bf_hi(h1), plo1 - bf_lo(h1));
            }
            #pragma unroll
            for (int ng2 = 0; ng2 < 4; ng2++) {
                u32 offV = (u32)((kt*16 + lr)*128 + ng2*32 + lhi*16);
                offV ^= (offV >> 3) & 0x70;
                u32 v4h[4], v4l[4];
                ldsm4t(v4h[0], v4h[1], v4h[2], v4h[3], sb + 4*8192 + offV);
                ldsm4t(v4l[0], v4l[1], v4l[2], v4l[3], sb + 5*8192 + offV);
                const int nt = ng2 * 2;
                mma16816(o[nt],   aph, v4h[0], v4h[1]);
                mma16816(o[nt],   apl, v4h[0], v4h[1]);
                mma16816(o[nt],   aph, v4l[0], v4l[1]);
                mma16816(o[nt+1], aph, v4h[2], v4h[3]);
                mma16816(o[nt+1], apl, v4h[2], v4h[3]);
                mma16816(o[nt+1], aph, v4l[2], v4l[3]);
            }
        }
    }

    // ---- normalize + store ----
    const float inv0 = 1.f / l0, inv1 = 1.f / l1;
    float* Og = Op + (rowbase + q0 + w*16 + r0) * D_ + colbase;
    #pragma unroll
    for (int nt = 0; nt < 8; nt++) {
        const int col = nt*8 + cq;
        *(float2*)(Og + col)          = make_float2(o[nt][0]*inv0, o[nt][1]*inv0);
        *(float2*)(Og + 8*D_ + col)   = make_float2(o[nt][2]*inv1, o[nt][3]*inv1);
    }
}

// ---------------------------------------------------------------------------
extern "C" void kernel_launch(void* const* d_in, const int* in_sizes, int n_in,
                              void* d_out, int out_size)
{
    const float* q  = (const float*)d_in[0];
    const float* k  = (const float*)d_in[1];
    const float* v  = (const float*)d_in[2];
    const float* Wq = (const float*)d_in[3];
    const float* bq = (const float*)d_in[4];
    const float* Wk = (const float*)d_in[5];
    const float* bk = (const float*)d_in[6];
    const float* Wv = (const float*)d_in[7];
    const float* bv = (const float*)d_in[8];
    const float* Wo = (const float*)d_in[9];
    const float* bo = (const float*)d_in[10];
    float* out = (float*)d_out;

    float *Qp, *Kp, *Vp, *Op;
    __nv_bfloat16 *xh, *xl, *wh, *wl, *qhp, *qlp, *khp, *klp, *vhp, *vlp;
    cudaGetSymbolAddress((void**)&Qp, g_Qp);
    cudaGetSymbolAddress((void**)&Kp, g_Kp);
    cudaGetSymbolAddress((void**)&Vp, g_Vp);
    cudaGetSymbolAddress((void**)&Op, g_Op);
    cudaGetSymbolAddress((void**)&xh, g_xh);
    cudaGetSymbolAddress((void**)&xl, g_xl);
    cudaGetSymbolAddress((void**)&wh, g_wh);
    cudaGetSymbolAddress((void**)&wl, g_wl);
    cudaGetSymbolAddress((void**)&qhp, g_qh);
    cudaGetSymbolAddress((void**)&qlp, g_ql);
    cudaGetSymbolAddress((void**)&khp, g_kh);
    cudaGetSymbolAddress((void**)&klp, g_kl);
    cudaGetSymbolAddress((void**)&vhp, g_vh);
    cudaGetSymbolAddress((void**)&vlp, g_vl);

    cudaFuncSetAttribute(gemm_mma,
                         cudaFuncAttributeMaxDynamicSharedMemorySize, GEMM_SMEM);
    cudaFuncSetAttribute(flash_attn_mma,
                         cudaFuncAttributeMaxDynamicSharedMemorySize, FA_SMEM);

    const int nx4 = M_*D_/4, nw4 = D_*D_/4;
    dim3 gg(D_/128, M_/128);

    // projections
    cvt_split<<<nx4/256, 256>>>(q, xh, xl, nx4);
    cvt_split<<<nw4/256, 256>>>(Wq, wh, wl, nw4);
    gemm_mma<<<gg, 256, GEMM_SMEM>>>(xh, xl, wh, wl, bq, Qp);
    cvt_split<<<nx4/256, 256>>>(k, xh, xl, nx4);
    cvt_split<<<nw4/256, 256>>>(Wk, wh, wl, nw4);
    gemm_mma<<<gg, 256, GEMM_SMEM>>>(xh, xl, wh, wl, bk, Kp);
    cvt_split<<<nx4/256, 256>>>(v, xh, xl, nx4);
    cvt_split<<<nw4/256, 256>>>(Wv, wh, wl, nw4);
    gemm_mma<<<gg, 256, GEMM_SMEM>>>(xh, xl, wh, wl, bv, Vp);

    // split projected Q/K/V for tensor-core attention
    cvt_split<<<nx4/256, 256>>>(Qp, qhp, qlp, nx4);
    cvt_split<<<nx4/256, 256>>>(Kp, khp, klp, nx4);
    cvt_split<<<nx4/256, 256>>>(Vp, vhp, vlp, nx4);

    flash_attn_mma<<<dim3(S_/64, B_*H_), 128, FA_SMEM>>>(qhp, qlp, khp, klp,
                                                          vhp, vlp, Op);

    // output projection
    cvt_split<<<nx4/256, 256>>>(Op, xh, xl, nx4);
    cvt_split<<<nw4/256, 256>>>(Wo, wh, wl, nw4);
    gemm_mma<<<gg, 256, GEMM_SMEM>>>(xh, xl, wh, wl, bo, out);
}

// round 11
// speedup vs baseline: 2.3007x; 1.4927x over previous
#include <cuda_runtime.h>
#include <cuda_bf16.h>
#include <math.h>
#include <stdint.h>

#define B_  4
#define S_  2048
#define D_  1024
#define H_  16
#define DK_ 64
#define M_  (B_*S_)   // 8192

typedef unsigned long long u64;
typedef unsigned int u32;

// ===================== warp-level tensor-core helpers (non-"a" ISA) ========
__device__ __forceinline__ u32 smem_to_u32(const void* p) {
    u32 a;
    asm("{ .reg .u64 t; cvta.to.shared.u64 t, %1; cvt.u32.u64 %0, t; }"
        : "=r"(a) : "l"(p));
    return a;
}
__device__ __forceinline__ void ldsm4(u32& r0, u32& r1, u32& r2, u32& r3, u32 a) {
    asm volatile("ldmatrix.sync.aligned.m8n8.x4.shared.b16 {%0,%1,%2,%3}, [%4];"
                 : "=r"(r0), "=r"(r1), "=r"(r2), "=r"(r3) : "r"(a));
}
__device__ __forceinline__ void ldsm4t(u32& r0, u32& r1, u32& r2, u32& r3, u32 a) {
    asm volatile("ldmatrix.sync.aligned.m8n8.x4.trans.shared.b16 {%0,%1,%2,%3}, [%4];"
                 : "=r"(r0), "=r"(r1), "=r"(r2), "=r"(r3) : "r"(a));
}
__device__ __forceinline__ void mma16816(float* c, const u32* a, u32 b0, u32 b1) {
    asm volatile("mma.sync.aligned.m16n8k16.row.col.f32.bf16.bf16.f32 "
                 "{%0,%1,%2,%3}, {%4,%5,%6,%7}, {%8,%9}, {%0,%1,%2,%3};"
                 : "+f"(c[0]), "+f"(c[1]), "+f"(c[2]), "+f"(c[3])
                 : "r"(a[0]), "r"(a[1]), "r"(a[2]), "r"(a[3]), "r"(b0), "r"(b1));
}
__device__ __forceinline__ u32 pkbf(float hi, float lo) {
    u32 d;
    asm("cvt.rn.bf16x2.f32 %0, %1, %2;" : "=r"(d) : "f"(hi), "f"(lo));
    return d;
}
__device__ __forceinline__ float bf_lo(u32 v) { return __int_as_float((int)(v << 16)); }
__device__ __forceinline__ float bf_hi(u32 v) { return __int_as_float((int)(v & 0xffff0000u)); }

#define CP_ASYNC16(saddr, gptr) \
    asm volatile("cp.async.cg.shared.global [%0], [%1], 16;" \
                 :: "r"(saddr), "l"(gptr))
#define CP_COMMIT()  asm volatile("cp.async.commit_group;" ::: "memory")
#define CP_WAIT0()   asm volatile("cp.async.wait_group 0;" ::: "memory")

// ---------------- scratch (device globals: allocation-free) ----------------
__device__ __nv_bfloat16 g_xh[M_*D_];
__device__ __nv_bfloat16 g_xl[M_*D_];
__device__ __nv_bfloat16 g_wh[D_*D_];
__device__ __nv_bfloat16 g_wl[D_*D_];
__device__ __nv_bfloat16 g_qh[M_*D_];
__device__ __nv_bfloat16 g_ql[M_*D_];
__device__ __nv_bfloat16 g_kh[M_*D_];
__device__ __nv_bfloat16 g_kl[M_*D_];
__device__ __nv_bfloat16 g_vh[M_*D_];
__device__ __nv_bfloat16 g_vl[M_*D_];

// ---------------------------------------------------------------------------
// split fp32 -> bf16 hi + bf16 lo
// ---------------------------------------------------------------------------
__global__ __launch_bounds__(256)
void cvt_split(const float* __restrict__ x, __nv_bfloat16* __restrict__ h,
               __nv_bfloat16* __restrict__ l, int n4)
{
    int i = blockIdx.x * 256 + threadIdx.x;
    if (i >= n4) return;
    float4 v = ((const float4*)x)[i];
    __nv_bfloat16 h0 = __float2bfloat16(v.x), h1 = __float2bfloat16(v.y);
    __nv_bfloat16 h2 = __float2bfloat16(v.z), h3 = __float2bfloat16(v.w);
    __nv_bfloat16 l0 = __float2bfloat16(v.x - __bfloat162float(h0));
    __nv_bfloat16 l1 = __float2bfloat16(v.y - __bfloat162float(h1));
    __nv_bfloat16 l2 = __float2bfloat16(v.z - __bfloat162float(h2));
    __nv_bfloat16 l3 = __float2bfloat16(v.w - __bfloat162float(h3));
    ((__nv_bfloat162*)h)[2*i+0] = __nv_bfloat162(h0, h1);
    ((__nv_bfloat162*)h)[2*i+1] = __nv_bfloat162(h2, h3);
    ((__nv_bfloat162*)l)[2*i+0] = __nv_bfloat162(l0, l1);
    ((__nv_bfloat162*)l)[2*i+1] = __nv_bfloat162(l2, l3);
}

// ---------------------------------------------------------------------------
// mma.sync bf16x3 GEMM.  OUT_SPLIT=1: write bf16 hi/lo; 0: write fp32.
// ---------------------------------------------------------------------------
#define GEMM_SMEM (4*16384)

template<int OUT_SPLIT>
__global__ __launch_bounds__(256)
void gemm_mma(const __nv_bfloat16* __restrict__ Ah, const __nv_bfloat16* __restrict__ Al,
              const __nv_bfloat16* __restrict__ Bh, const __nv_bfloat16* __restrict__ Bl,
              const float* __restrict__ bias, float* __restrict__ Cf,
              __nv_bfloat16* __restrict__ Ch, __nv_bfloat16* __restrict__ Cl)
{
    extern __shared__ char smc[];
    const u32 sb   = smem_to_u32(smc);
    const int tid  = threadIdx.x, wid = tid >> 5, lane = tid & 31;
    const int brow = blockIdx.y * 128, bcol = blockIdx.x * 128;
    const int wm   = wid & 1;
    const int wn   = wid >> 1;
    const int lr   = lane & 15, lhi = lane >> 4;

    float acc[4][4][4];
    #pragma unroll
    for (int mt = 0; mt < 4; mt++)
        #pragma unroll
        for (int nt = 0; nt < 4; nt++)
            #pragma unroll
            for (int r = 0; r < 4; r++) acc[mt][nt][r] = 0.f;

    const __nv_bfloat16* gsrc[4] = { Ah, Al, Bh, Bl };

    for (int c = 0; c < 16; c++) {
        const int k0 = c * 64;
        #pragma unroll
        for (int t2 = 0; t2 < 4; t2++) {
            const __nv_bfloat16* g = gsrc[t2];
            const int rowbase = (t2 < 2) ? brow : bcol;
            char* sm = smc + t2 * 16384;
            #pragma unroll
            for (int seg = tid; seg < 1024; seg += 256) {
                int r = seg >> 3, s = seg & 7;
                uint4 v = *(const uint4*)(g + (size_t)(rowbase + r) * D_ + k0 + s*8);
                u32 off = r*128 + s*16;
                *(uint4*)(sm + (off ^ ((off >> 3) & 0x70))) = v;
            }
        }
        __syncthreads();

        #pragma unroll
        for (int ks = 0; ks < 4; ks++) {
            u32 ah[4][4], al[4][4];
            #pragma unroll
            for (int mt = 0; mt < 4; mt++) {
                int r = wm*64 + mt*16 + lr;
                u32 off = (u32)(r*128 + (ks*2 + lhi)*16);
                off ^= (off >> 3) & 0x70;
                ldsm4(ah[mt][0], ah[mt][1], ah[mt][2], ah[mt][3], sb + off);
                ldsm4(al[mt][0], al[mt][1], al[mt][2], al[mt][3], sb + 16384 + off);
            }
            #pragma unroll
            for (int np = 0; np < 2; np++) {
                int r = wn*32 + np*16 + lr;
                u32 off = (u32)(r*128 + (ks*2 + lhi)*16);
                off ^= (off >> 3) & 0x70;
                u32 bh[4], bl[4];
                ldsm4(bh[0], bh[1], bh[2], bh[3], sb + 2*16384 + off);
                ldsm4(bl[0], bl[1], bl[2], bl[3], sb + 3*16384 + off);
                #pragma unroll
                for (int half = 0; half < 2; half++) {
                    const int nt = np*2 + half;
                    const u32 fh0 = bh[half], fh1 = bh[half+2];
                    const u32 fl0 = bl[half], fl1 = bl[half+2];
                    #pragma unroll
                    for (int mt = 0; mt < 4; mt++) {
                        mma16816(acc[mt][nt], ah[mt], fh0, fh1);
                        mma16816(acc[mt][nt], al[mt], fh0, fh1);
                        mma16816(acc[mt][nt], ah[mt], fl0, fl1);
                    }
                }
            }
        }
        __syncthreads();
    }

    const int r0 = lane >> 2, c0 = (lane & 3) * 2;
    #pragma unroll
    for (int nt = 0; nt < 4; nt++) {
        const int col = bcol + wn*32 + nt*8 + c0;
        float2 bv = *(const float2*)&bias[col];
        #pragma unroll
        for (int mt = 0; mt < 4; mt++) {
            const int row = brow + wm*64 + mt*16 + r0;
            float a0 = acc[mt][nt][0] + bv.x, a1 = acc[mt][nt][1] + bv.y;
            float a2 = acc[mt][nt][2] + bv.x, a3 = acc[mt][nt][3] + bv.y;
            if (OUT_SPLIT) {
                __nv_bfloat16 h0 = __float2bfloat16(a0), h1 = __float2bfloat16(a1);
                __nv_bfloat16 h2 = __float2bfloat16(a2), h3 = __float2bfloat16(a3);
                __nv_bfloat16 e0 = __float2bfloat16(a0 - __bfloat162float(h0));
                __nv_bfloat16 e1 = __float2bfloat16(a1 - __bfloat162float(h1));
                __nv_bfloat16 e2 = __float2bfloat16(a2 - __bfloat162float(h2));
                __nv_bfloat16 e3 = __float2bfloat16(a3 - __bfloat162float(h3));
                *(__nv_bfloat162*)(Ch + (size_t)row     * D_ + col) = __nv_bfloat162(h0, h1);
                *(__nv_bfloat162*)(Ch + (size_t)(row+8) * D_ + col) = __nv_bfloat162(h2, h3);
                *(__nv_bfloat162*)(Cl + (size_t)row     * D_ + col) = __nv_bfloat162(e0, e1);
                *(__nv_bfloat162*)(Cl + (size_t)(row+8) * D_ + col) = __nv_bfloat162(e2, e3);
            } else {
                *(float2*)(Cf + (size_t)row     * D_ + col) = make_float2(a0, a1);
                *(float2*)(Cf + (size_t)(row+8) * D_ + col) = make_float2(a2, a3);
            }
        }
    }
}

// ---------------------------------------------------------------------------
// Causal flash attention, tensor cores, bf16x3 splits, fp32 softmax.
// Block = (b,h) x 128 q-rows, 8 warps (16 rows each). K/V 64-row tiles,
// cp.async double-buffered. Output written as bf16 hi/lo split.
// smem: Qh 16K | Ql 16K | 2 x [Kh 8K | Kl 8K | Vh 8K | Vl 8K]
// ---------------------------------------------------------------------------
#define FA_SMEM (32768 + 2*32768)   // 96 KB

__device__ __forceinline__ void fa_load_kv(char* dst,
    const __nv_bfloat16* __restrict__ kh, const __nv_bfloat16* __restrict__ kl,
    const __nv_bfloat16* __restrict__ vh, const __nv_bfloat16* __restrict__ vl,
    size_t gbase, int tid)
{
    #pragma unroll
    for (int seg = tid; seg < 512; seg += 256) {
        int r = seg >> 3, c = seg & 7;
        u32 off = (u32)(r*128 + c*16); off ^= (off >> 3) & 0x70;
        size_t g = gbase + (size_t)r * D_ + c*8;
        u32 s0 = smem_to_u32(dst + off);
        CP_ASYNC16(s0,         kh + g);
        CP_ASYNC16(s0 + 8192,  kl + g);
        CP_ASYNC16(s0 + 16384, vh + g);
        CP_ASYNC16(s0 + 24576, vl + g);
    }
    CP_COMMIT();
}

__global__ __launch_bounds__(256)
void flash_attn_mma(const __nv_bfloat16* __restrict__ qh, const __nv_bfloat16* __restrict__ ql,
                    const __nv_bfloat16* __restrict__ kh, const __nv_bfloat16* __restrict__ kl,
                    const __nv_bfloat16* __restrict__ vh, const __nv_bfloat16* __restrict__ vl,
                    __nv_bfloat16* __restrict__ oh, __nv_bfloat16* __restrict__ ol)
{
    extern __shared__ char smf[];
    const u32 sb = smem_to_u32(smf);
    const int tid = threadIdx.x, w = tid >> 5, lane = tid & 31;
    const int qb = (int)gridDim.x - 1 - (int)blockIdx.x;   // big tiles first
    const int q0 = qb * 128;
    const int b = blockIdx.y >> 4, h = blockIdx.y & 15;
    const size_t rowbase = (size_t)b * S_;
    const size_t colbase = (size_t)h * 64;

    const int lr = lane & 15, lhi = lane >> 4;
    const int r0 = lane >> 2, cq = (lane & 3) * 2;
    const int rg = w*16 + r0;   // row within 128-row q tile

    // Q hi/lo tiles: 128 rows x 64 bf16 each, SW128 swizzle
    {
        const __nv_bfloat16* gh = qh + (rowbase + q0) * D_ + colbase;
        const __nv_bfloat16* gl = ql + (rowbase + q0) * D_ + colbase;
        #pragma unroll
        for (int seg = tid; seg < 1024; seg += 256) {
            int r = seg >> 3, c = seg & 7;
            u32 off = (u32)(r*128 + c*16); off ^= (off >> 3) & 0x70;
            *(uint4*)(smf + off)         = *(const uint4*)(gh + (size_t)r * D_ + c*8);
            *(uint4*)(smf + 16384 + off) = *(const uint4*)(gl + (size_t)r * D_ + c*8);
        }
    }

    const int ttmax = 2*qb + 1;
    // preload kv tile 0 into buffer 0
    fa_load_kv(smf + 32768, kh, kl, vh, vl, rowbase * D_ + colbase, tid);

    float m0 = -INFINITY, m1 = -INFINITY, l0 = 0.f, l1 = 0.f;
    float o[8][4];
    #pragma unroll
    for (int nt = 0; nt < 8; nt++)
        #pragma unroll
        for (int r = 0; r < 4; r++) o[nt][r] = 0.f;

    for (int tt = 0; tt <= ttmax; tt++) {
        CP_WAIT0();
        __syncthreads();   // kv tile tt ready; all warps done with buffer tt-1
        if (tt < ttmax)
            fa_load_kv(smf + 32768 + ((tt+1)&1)*32768, kh, kl, vh, vl,
                       (rowbase + (size_t)(tt+1)*64) * D_ + colbase, tid);

        const int dcol = tt*64 - q0;             // col offset rel. to q tile rows
        if (dcol > w*16 + 15) continue;          // warp fully masked

        const u32 sk = sb + 32768u + (u32)(tt & 1) * 32768u;

        // ---- S = Q K^T ----
        float s[8][4];
        #pragma unroll
        for (int nt = 0; nt < 8; nt++)
            #pragma unroll
            for (int r = 0; r < 4; r++) s[nt][r] = 0.f;

        #pragma unroll
        for (int ks = 0; ks < 4; ks++) {
            u32 offA = (u32)((w*16 + lr)*128 + (ks*2 + lhi)*16);
            offA ^= (offA >> 3) & 0x70;
            u32 aqh[4], aql[4];
            ldsm4(aqh[0], aqh[1], aqh[2], aqh[3], sb + offA);
            ldsm4(aql[0], aql[1], aql[2], aql[3], sb + 16384 + offA);
            #pragma unroll
            for (int np = 0; np < 4; np++) {
                u32 offB = (u32)((np*16 + lr)*128 + (ks*2 + lhi)*16);
                offB ^= (offB >> 3) & 0x70;
                u32 bh[4], bl[4];
                ldsm4(bh[0], bh[1], bh[2], bh[3], sk + offB);
                ldsm4(bl[0], bl[1], bl[2], bl[3], sk + 8192 + offB);
                #pragma unroll
                for (int half = 0; half < 2; half++) {
                    const int nt = np*2 + half;
                    const u32 f0 = bh[half], f1 = bh[half+2];
                    mma16816(s[nt], aqh, f0, f1);
                    mma16816(s[nt], aql, f0, f1);
                    mma16816(s[nt], aqh, bl[half], bl[half+2]);
                }
            }
        }

        // ---- causal mask (diagonal region only) ----
        if (dcol + 63 > w*16) {
            #pragma unroll
            for (int nt = 0; nt < 8; nt++) {
                const int cc = nt*8 + cq + dcol;
                if (cc     > rg)     s[nt][0] = -INFINITY;
                if (cc + 1 > rg)     s[nt][1] = -INFINITY;
                if (cc     > rg + 8) s[nt][2] = -INFINITY;
                if (cc + 1 > rg + 8) s[nt][3] = -INFINITY;
            }
        }

        // ---- online softmax (1/8 scale folded into exp args) ----
        float rm0 = -INFINITY, rm1 = -INFINITY;
        #pragma unroll
        for (int nt = 0; nt < 8; nt++) {
            rm0 = fmaxf(rm0, fmaxf(s[nt][0], s[nt][1]));
            rm1 = fmaxf(rm1, fmaxf(s[nt][2], s[nt][3]));
        }
        rm0 = fmaxf(rm0, __shfl_xor_sync(0xffffffffu, rm0, 1));
        rm0 = fmaxf(rm0, __shfl_xor_sync(0xffffffffu, rm0, 2));
        rm1 = fmaxf(rm1, __shfl_xor_sync(0xffffffffu, rm1, 1));
        rm1 = fmaxf(rm1, __shfl_xor_sync(0xffffffffu, rm1, 2));
        float mn0 = fmaxf(m0, rm0), mn1 = fmaxf(m1, rm1);
        float alpha0 = __expf(0.125f * (m0 - mn0));
        float alpha1 = __expf(0.125f * (m1 - mn1));
        m0 = mn0; m1 = mn1;
        const float m08 = mn0 * 0.125f, m18 = mn1 * 0.125f;
        float rs0 = 0.f, rs1 = 0.f;
        #pragma unroll
        for (int nt = 0; nt < 8; nt++) {
            s[nt][0] = __expf(fmaf(s[nt][0], 0.125f, -m08));
            s[nt][1] = __expf(fmaf(s[nt][1], 0.125f, -m08));
            s[nt][2] = __expf(fmaf(s[nt][2], 0.125f, -m18));
            s[nt][3] = __expf(fmaf(s[nt][3], 0.125f, -m18));
            rs0 += s[nt][0] + s[nt][1];
            rs1 += s[nt][2] + s[nt][3];
        }
        rs0 += __shfl_xor_sync(0xffffffffu, rs0, 1);
        rs0 += __shfl_xor_sync(0xffffffffu, rs0, 2);
        rs1 += __shfl_xor_sync(0xffffffffu, rs1, 1);
        rs1 += __shfl_xor_sync(0xffffffffu, rs1, 2);
        l0 = l0 * alpha0 + rs0;
        l1 = l1 * alpha1 + rs1;
        #pragma unroll
        for (int nt = 0; nt < 8; nt++) {
            o[nt][0] *= alpha0; o[nt][1] *= alpha0;
            o[nt][2] *= alpha1; o[nt][3] *= alpha1;
        }

        // ---- O += P V ----
        #pragma unroll
        for (int kt = 0; kt < 4; kt++) {
            u32 aph[4], apl[4];
            #pragma unroll
            for (int half = 0; half < 2; half++) {
                const float plo0 = s[2*kt + half][0], phi0 = s[2*kt + half][1];
                const float plo1 = s[2*kt + half][2], phi1 = s[2*kt + half][3];
                u32 h0 = pkbf(phi0, plo0);
                u32 h1 = pkbf(phi1, plo1);
                aph[0 + 2*half] = h0;
                aph[1 + 2*half] = h1;
                apl[0 + 2*half] = pkbf(phi0 - bf_hi(h0), plo0 - bf_lo(h0));
                apl[1 + 2*half] = pkbf(phi1 - bf_hi(h1), plo1 - bf_lo(h1));
            }
            #pragma unroll
            for (int ng2 = 0; ng2 < 4; ng2++) {
                u32 offV = (u32)((kt*16 + lr)*128 + ng2*32 + lhi*16);
                offV ^= (offV >> 3) & 0x70;
                u32 v4h[4], v4l[4];
                ldsm4t(v4h[0], v4h[1], v4h[2], v4h[3], sk + 16384 + offV);
                ldsm4t(v4l[0], v4l[1], v4l[2], v4l[3], sk + 24576 + offV);
                const int nt = ng2 * 2;
                mma16816(o[nt],   aph, v4h[0], v4h[1]);
                mma16816(o[nt],   apl, v4h[0], v4h[1]);
                mma16816(o[nt],   aph, v4l[0], v4l[1]);
                mma16816(o[nt+1], aph, v4h[2], v4h[3]);
                mma16816(o[nt+1], apl, v4h[2], v4h[3]);
                mma16816(o[nt+1], aph, v4l[2], v4l[3]);
            }
        }
    }

    // ---- normalize + bf16 hi/lo split store ----
    const float inv0 = 1.f / l0, inv1 = 1.f / l1;
    const size_t orow = (rowbase + q0 + rg) * D_ + colbase;
    #pragma unroll
    for (int nt = 0; nt < 8; nt++) {
        const int col = nt*8 + cq;
        float a0 = o[nt][0]*inv0, a1 = o[nt][1]*inv0;
        float a2 = o[nt][2]*inv1, a3 = o[nt][3]*inv1;
        __nv_bfloat16 h0 = __float2bfloat16(a0), h1 = __float2bfloat16(a1);
        __nv_bfloat16 h2 = __float2bfloat16(a2), h3 = __float2bfloat16(a3);
        __nv_bfloat16 e0 = __float2bfloat16(a0 - __bfloat162float(h0));
        __nv_bfloat16 e1 = __float2bfloat16(a1 - __bfloat162float(h1));
        __nv_bfloat16 e2 = __float2bfloat16(a2 - __bfloat162float(h2));
        __nv_bfloat16 e3 = __float2bfloat16(a3 - __bfloat162float(h3));
        *(__nv_bfloat162*)(oh + orow + col)        = __nv_bfloat162(h0, h1);
        *(__nv_bfloat162*)(oh + orow + 8*D_ + col) = __nv_bfloat162(h2, h3);
        *(__nv_bfloat162*)(ol + orow + col)        = __nv_bfloat162(e0, e1);
        *(__nv_bfloat162*)(ol + orow + 8*D_ + col) = __nv_bfloat162(e2, e3);
    }
}

// ---------------------------------------------------------------------------
extern "C" void kernel_launch(void* const* d_in, const int* in_sizes, int n_in,
                              void* d_out, int out_size)
{
    const float* q  = (const float*)d_in[0];
    const float* k  = (const float*)d_in[1];
    const float* v  = (const float*)d_in[2];
    const float* Wq = (const float*)d_in[3];
    const float* bq = (const float*)d_in[4];
    const float* Wk = (const float*)d_in[5];
    const float* bk = (const float*)d_in[6];
    const float* Wv = (const float*)d_in[7];
    const float* bv = (const float*)d_in[8];
    const float* Wo = (const float*)d_in[9];
    const float* bo = (const float*)d_in[10];
    float* out = (float*)d_out;

    __nv_bfloat16 *xh, *xl, *wh, *wl, *qhp, *qlp, *khp, *klp, *vhp, *vlp;
    cudaGetSymbolAddress((void**)&xh, g_xh);
    cudaGetSymbolAddress((void**)&xl, g_xl);
    cudaGetSymbolAddress((void**)&wh, g_wh);
    cudaGetSymbolAddress((void**)&wl, g_wl);
    cudaGetSymbolAddress((void**)&qhp, g_qh);
    cudaGetSymbolAddress((void**)&qlp, g_ql);
    cudaGetSymbolAddress((void**)&khp, g_kh);
    cudaGetSymbolAddress((void**)&klp, g_kl);
    cudaGetSymbolAddress((void**)&vhp, g_vh);
    cudaGetSymbolAddress((void**)&vlp, g_vl);

    cudaFuncSetAttribute(gemm_mma<1>,
                         cudaFuncAttributeMaxDynamicSharedMemorySize, GEMM_SMEM);
    cudaFuncSetAttribute(gemm_mma<0>,
                         cudaFuncAttributeMaxDynamicSharedMemorySize, GEMM_SMEM);
    cudaFuncSetAttribute(flash_attn_mma,
                         cudaFuncAttributeMaxDynamicSharedMemorySize, FA_SMEM);

    const int nx4 = M_*D_/4, nw4 = D_*D_/4;
    dim3 gg(D_/128, M_/128);

    // projections (outputs written directly as bf16 hi/lo splits)
    cvt_split<<<nx4/256, 256>>>(q, xh, xl, nx4);
    cvt_split<<<nw4/256, 256>>>(Wq, wh, wl, nw4);
    gemm_mma<1><<<gg, 256, GEMM_SMEM>>>(xh, xl, wh, wl, bq, nullptr, qhp, qlp);
    cvt_split<<<nx4/256, 256>>>(k, xh, xl, nx4);
    cvt_split<<<nw4/256, 256>>>(Wk, wh, wl, nw4);
    gemm_mma<1><<<gg, 256, GEMM_SMEM>>>(xh, xl, wh, wl, bk, nullptr, khp, klp);
    cvt_split<<<nx4/256, 256>>>(v, xh, xl, nx4);
    cvt_split<<<nw4/256, 256>>>(Wv, wh, wl, nw4);
    gemm_mma<1><<<gg, 256, GEMM_SMEM>>>(xh, xl, wh, wl, bv, nullptr, vhp, vlp);

    // attention (reads splits, writes bf16 hi/lo splits for the O projection)
    flash_attn_mma<<<dim3(S_/128, B_*H_), 256, FA_SMEM>>>(qhp, qlp, khp, klp,
                                                           vhp, vlp, xh, xl);

    // output projection (fp32 out)
    cvt_split<<<nw4/256, 256>>>(Wo, wh, wl, nw4);
    gemm_mma<0><<<gg, 256, GEMM_SMEM>>>(xh, xl, wh, wl, bo, out, nullptr, nullptr);
}

// round 12
// speedup vs baseline: 2.4748x; 1.0757x over previous
#include <cuda_runtime.h>
#include <cuda_bf16.h>
#include <math.h>
#include <stdint.h>

#define B_  4
#define S_  2048
#define D_  1024
#define H_  16
#define DK_ 64
#define M_  (B_*S_)   // 8192

typedef unsigned long long u64;
typedef unsigned int u32;

// ===================== warp-level tensor-core helpers (non-"a" ISA) ========
__device__ __forceinline__ u32 smem_to_u32(const void* p) {
    u32 a;
    asm("{ .reg .u64 t; cvta.to.shared.u64 t, %1; cvt.u32.u64 %0, t; }"
        : "=r"(a) : "l"(p));
    return a;
}
__device__ __forceinline__ void ldsm4(u32& r0, u32& r1, u32& r2, u32& r3, u32 a) {
    asm volatile("ldmatrix.sync.aligned.m8n8.x4.shared.b16 {%0,%1,%2,%3}, [%4];"
                 : "=r"(r0), "=r"(r1), "=r"(r2), "=r"(r3) : "r"(a));
}
__device__ __forceinline__ void ldsm4t(u32& r0, u32& r1, u32& r2, u32& r3, u32 a) {
    asm volatile("ldmatrix.sync.aligned.m8n8.x4.trans.shared.b16 {%0,%1,%2,%3}, [%4];"
                 : "=r"(r0), "=r"(r1), "=r"(r2), "=r"(r3) : "r"(a));
}
__device__ __forceinline__ void mma16816(float* c, const u32* a, u32 b0, u32 b1) {
    asm volatile("mma.sync.aligned.m16n8k16.row.col.f32.bf16.bf16.f32 "
                 "{%0,%1,%2,%3}, {%4,%5,%6,%7}, {%8,%9}, {%0,%1,%2,%3};"
                 : "+f"(c[0]), "+f"(c[1]), "+f"(c[2]), "+f"(c[3])
                 : "r"(a[0]), "r"(a[1]), "r"(a[2]), "r"(a[3]), "r"(b0), "r"(b1));
}
// cvt.rn.bf16x2.f32 d, a, b  -> upper half = bf16(a), lower half = bf16(b)
__device__ __forceinline__ u32 pkbf(float hi, float lo) {
    u32 d;
    asm("cvt.rn.bf16x2.f32 %0, %1, %2;" : "=r"(d) : "f"(hi), "f"(lo));
    return d;
}
__device__ __forceinline__ float bf_lo(u32 v) { return __int_as_float((int)(v << 16)); }
__device__ __forceinline__ float bf_hi(u32 v) { return __int_as_float((int)(v & 0xffff0000u)); }

// split 8 fp32 -> 4 bf16x2 hi + 4 bf16x2 lo (memory element order preserved)
__device__ __forceinline__ void cvt8(float4 v0, float4 v1, u32* h, u32* l) {
    h[0] = pkbf(v0.y, v0.x);
    l[0] = pkbf(v0.y - bf_hi(h[0]), v0.x - bf_lo(h[0]));
    h[1] = pkbf(v0.w, v0.z);
    l[1] = pkbf(v0.w - bf_hi(h[1]), v0.z - bf_lo(h[1]));
    h[2] = pkbf(v1.y, v1.x);
    l[2] = pkbf(v1.y - bf_hi(h[2]), v1.x - bf_lo(h[2]));
    h[3] = pkbf(v1.w, v1.z);
    l[3] = pkbf(v1.w - bf_hi(h[3]), v1.z - bf_lo(h[3]));
}

#define CP_ASYNC16(saddr, gptr) \
    asm volatile("cp.async.cg.shared.global [%0], [%1], 16;" \
                 :: "r"(saddr), "l"(gptr))
#define CP_COMMIT()  asm volatile("cp.async.commit_group;" ::: "memory")
#define CP_WAIT0()   asm volatile("cp.async.wait_group 0;" ::: "memory")

// ---------------- scratch (device globals: allocation-free) ----------------
__device__ __nv_bfloat16 g_xh[M_*D_];
__device__ __nv_bfloat16 g_xl[M_*D_];
__device__ __nv_bfloat16 g_qh[M_*D_];
__device__ __nv_bfloat16 g_ql[M_*D_];
__device__ __nv_bfloat16 g_kh[M_*D_];
__device__ __nv_bfloat16 g_kl[M_*D_];
__device__ __nv_bfloat16 g_vh[M_*D_];
__device__ __nv_bfloat16 g_vl[M_*D_];

// ---------------------------------------------------------------------------
// Fused-split mma.sync bf16x3 GEMM:
//   C[z] = A[z][M,K] @ W[z][N,K]^T + bias[z]
// fp32 operands are split to bf16 hi/lo DURING the smem fill (no separate
// conversion kernels). blockIdx.z selects the projection.
// A_FP32: A[z] is fp32 (else pre-split bf16 hi/lo in A0/A1).
// OUT_SPLIT: write bf16 hi/lo split; else fp32.
// ---------------------------------------------------------------------------
#define GEMM_SMEM (4*16384)

struct GArgs {
    const void*  A0[3];    // fp32 A  (A_FP32) or bf16 Ah
    const void*  A1[3];    // bf16 Al (if !A_FP32)
    const float* W[3];     // fp32 weights [N,K]
    const float* bias[3];
    __nv_bfloat16* Ch[3];
    __nv_bfloat16* Cl[3];
    float* Cf[3];
};

template<int A_FP32, int OUT_SPLIT>
__global__ __launch_bounds__(256)
void gemm_mma(GArgs ga)
{
    extern __shared__ char smc[];
    const u32 sb   = smem_to_u32(smc);
    const int tid  = threadIdx.x, wid = tid >> 5, lane = tid & 31;
    const int z    = blockIdx.z;
    const int brow = blockIdx.y * 128, bcol = blockIdx.x * 128;
    const int wm   = wid & 1;
    const int wn   = wid >> 1;
    const int lr   = lane & 15, lhi = lane >> 4;

    const float* Wg = ga.W[z];
    const float* bias = ga.bias[z];

    float acc[4][4][4];
    #pragma unroll
    for (int mt = 0; mt < 4; mt++)
        #pragma unroll
        for (int nt = 0; nt < 4; nt++)
            #pragma unroll
            for (int r = 0; r < 4; r++) acc[mt][nt][r] = 0.f;

    for (int c = 0; c < 16; c++) {
        const int k0 = c * 64;

        // ---- A tiles (hi -> smc+0, lo -> smc+16K) ----
        if (A_FP32) {
            const float* Af = (const float*)ga.A0[z];
            #pragma unroll
            for (int seg = tid; seg < 1024; seg += 256) {
                int r = seg >> 3, s = seg & 7;
                const float* gp = Af + (size_t)(brow + r) * D_ + k0 + s*8;
                float4 v0 = *(const float4*)gp;
                float4 v1 = *(const float4*)(gp + 4);
                u32 h[4], l[4];
                cvt8(v0, v1, h, l);
                u32 off = r*128 + s*16; off ^= (off >> 3) & 0x70;
                *(uint4*)(smc + off)         = make_uint4(h[0], h[1], h[2], h[3]);
                *(uint4*)(smc + 16384 + off) = make_uint4(l[0], l[1], l[2], l[3]);
            }
        } else {
            const __nv_bfloat16* Ah = (const __nv_bfloat16*)ga.A0[z];
            const __nv_bfloat16* Al = (const __nv_bfloat16*)ga.A1[z];
            #pragma unroll
            for (int seg = tid; seg < 1024; seg += 256) {
                int r = seg >> 3, s = seg & 7;
                u32 off = r*128 + s*16; off ^= (off >> 3) & 0x70;
                *(uint4*)(smc + off) =
                    *(const uint4*)(Ah + (size_t)(brow + r) * D_ + k0 + s*8);
                *(uint4*)(smc + 16384 + off) =
                    *(const uint4*)(Al + (size_t)(brow + r) * D_ + k0 + s*8);
            }
        }

        // ---- W tiles, always fp32 -> split (hi -> smc+32K, lo -> smc+48K) ----
        #pragma unroll
        for (int seg = tid; seg < 1024; seg += 256) {
            int r = seg >> 3, s = seg & 7;
            const float* gp = Wg + (size_t)(bcol + r) * D_ + k0 + s*8;
            float4 v0 = *(const float4*)gp;
            float4 v1 = *(const float4*)(gp + 4);
            u32 h[4], l[4];
            cvt8(v0, v1, h, l);
            u32 off = r*128 + s*16; off ^= (off >> 3) & 0x70;
            *(uint4*)(smc + 2*16384 + off) = make_uint4(h[0], h[1], h[2], h[3]);
            *(uint4*)(smc + 3*16384 + off) = make_uint4(l[0], l[1], l[2], l[3]);
        }
        __syncthreads();

        #pragma unroll
        for (int ks = 0; ks < 4; ks++) {
            u32 ah[4][4], al[4][4];
            #pragma unroll
            for (int mt = 0; mt < 4; mt++) {
                int r = wm*64 + mt*16 + lr;
                u32 off = (u32)(r*128 + (ks*2 + lhi)*16);
                off ^= (off >> 3) & 0x70;
                ldsm4(ah[mt][0], ah[mt][1], ah[mt][2], ah[mt][3], sb + off);
                ldsm4(al[mt][0], al[mt][1], al[mt][2], al[mt][3], sb + 16384 + off);
            }
            #pragma unroll
            for (int np = 0; np < 2; np++) {
                int r = wn*32 + np*16 + lr;
                u32 off = (u32)(r*128 + (ks*2 + lhi)*16);
                off ^= (off >> 3) & 0x70;
                u32 bh[4], bl[4];
                ldsm4(bh[0], bh[1], bh[2], bh[3], sb + 2*16384 + off);
                ldsm4(bl[0], bl[1], bl[2], bl[3], sb + 3*16384 + off);
                #pragma unroll
                for (int half = 0; half < 2; half++) {
                    const int nt = np*2 + half;
                    const u32 fh0 = bh[half], fh1 = bh[half+2];
                    const u32 fl0 = bl[half], fl1 = bl[half+2];
                    #pragma unroll
                    for (int mt = 0; mt < 4; mt++) {
                        mma16816(acc[mt][nt], ah[mt], fh0, fh1);
                        mma16816(acc[mt][nt], al[mt], fh0, fh1);
                        mma16816(acc[mt][nt], ah[mt], fl0, fl1);
                    }
                }
            }
        }
        __syncthreads();
    }

    const int r0 = lane >> 2, c0 = (lane & 3) * 2;
    #pragma unroll
    for (int nt = 0; nt < 4; nt++) {
        const int col = bcol + wn*32 + nt*8 + c0;
        float2 bv = *(const float2*)&bias[col];
        #pragma unroll
        for (int mt = 0; mt < 4; mt++) {
            const int row = brow + wm*64 + mt*16 + r0;
            float a0 = acc[mt][nt][0] + bv.x, a1 = acc[mt][nt][1] + bv.y;
            float a2 = acc[mt][nt][2] + bv.x, a3 = acc[mt][nt][3] + bv.y;
            if (OUT_SPLIT) {
                __nv_bfloat16* Ch = ga.Ch[z];
                __nv_bfloat16* Cl = ga.Cl[z];
                u32 h01 = pkbf(a1, a0);
                u32 h23 = pkbf(a3, a2);
                u32 l01 = pkbf(a1 - bf_hi(h01), a0 - bf_lo(h01));
                u32 l23 = pkbf(a3 - bf_hi(h23), a2 - bf_lo(h23));
                *(u32*)(Ch + (size_t)row     * D_ + col) = h01;
                *(u32*)(Ch + (size_t)(row+8) * D_ + col) = h23;
                *(u32*)(Cl + (size_t)row     * D_ + col) = l01;
                *(u32*)(Cl + (size_t)(row+8) * D_ + col) = l23;
            } else {
                float* Cf = ga.Cf[z];
                *(float2*)(Cf + (size_t)row     * D_ + col) = make_float2(a0, a1);
                *(float2*)(Cf + (size_t)(row+8) * D_ + col) = make_float2(a2, a3);
            }
        }
    }
}

// ---------------------------------------------------------------------------
// Causal flash attention, tensor cores, bf16x3 splits, fp32 softmax.
// Block = (b,h) x 128 q-rows, 8 warps. K/V 64-row tiles, cp.async
// double-buffered. Output written as bf16 hi/lo split.
// ---------------------------------------------------------------------------
#define FA_SMEM (32768 + 2*32768)   // 96 KB

__device__ __forceinline__ void fa_load_kv(char* dst,
    const __nv_bfloat16* __restrict__ kh, const __nv_bfloat16* __restrict__ kl,
    const __nv_bfloat16* __restrict__ vh, const __nv_bfloat16* __restrict__ vl,
    size_t gbase, int tid)
{
    #pragma unroll
    for (int seg = tid; seg < 512; seg += 256) {
        int r = seg >> 3, c = seg & 7;
        u32 off = (u32)(r*128 + c*16); off ^= (off >> 3) & 0x70;
        size_t g = gbase + (size_t)r * D_ + c*8;
        u32 s0 = smem_to_u32(dst + off);
        CP_ASYNC16(s0,         kh + g);
        CP_ASYNC16(s0 + 8192,  kl + g);
        CP_ASYNC16(s0 + 16384, vh + g);
        CP_ASYNC16(s0 + 24576, vl + g);
    }
    CP_COMMIT();
}

__global__ __launch_bounds__(256)
void flash_attn_mma(const __nv_bfloat16* __restrict__ qh, const __nv_bfloat16* __restrict__ ql,
                    const __nv_bfloat16* __restrict__ kh, const __nv_bfloat16* __restrict__ kl,
                    const __nv_bfloat16* __restrict__ vh, const __nv_bfloat16* __restrict__ vl,
                    __nv_bfloat16* __restrict__ oh, __nv_bfloat16* __restrict__ ol)
{
    extern __shared__ char smf[];
    const u32 sb = smem_to_u32(smf);
    const int tid = threadIdx.x, w = tid >> 5, lane = tid & 31;
    const int qb = (int)gridDim.x - 1 - (int)blockIdx.x;   // big tiles first
    const int q0 = qb * 128;
    const int b = blockIdx.y >> 4, h = blockIdx.y & 15;
    const size_t rowbase = (size_t)b * S_;
    const size_t colbase = (size_t)h * 64;

    const int lr = lane & 15, lhi = lane >> 4;
    const int r0 = lane >> 2, cq = (lane & 3) * 2;
    const int rg = w*16 + r0;

    {
        const __nv_bfloat16* gh = qh + (rowbase + q0) * D_ + colbase;
        const __nv_bfloat16* gl = ql + (rowbase + q0) * D_ + colbase;
        #pragma unroll
        for (int seg = tid; seg < 1024; seg += 256) {
            int r = seg >> 3, c = seg & 7;
            u32 off = (u32)(r*128 + c*16); off ^= (off >> 3) & 0x70;
            *(uint4*)(smf + off)         = *(const uint4*)(gh + (size_t)r * D_ + c*8);
            *(uint4*)(smf + 16384 + off) = *(const uint4*)(gl + (size_t)r * D_ + c*8);
        }
    }

    const int ttmax = 2*qb + 1;
    fa_load_kv(smf + 32768, kh, kl, vh, vl, rowbase * D_ + colbase, tid);

    float m0 = -INFINITY, m1 = -INFINITY, l0 = 0.f, l1 = 0.f;
    float o[8][4];
    #pragma unroll
    for (int nt = 0; nt < 8; nt++)
        #pragma unroll
        for (int r = 0; r < 4; r++) o[nt][r] = 0.f;

    for (int tt = 0; tt <= ttmax; tt++) {
        CP_WAIT0();
        __syncthreads();
        if (tt < ttmax)
            fa_load_kv(smf + 32768 + ((tt+1)&1)*32768, kh, kl, vh, vl,
                       (rowbase + (size_t)(tt+1)*64) * D_ + colbase, tid);

        const int dcol = tt*64 - q0;
        if (dcol > w*16 + 15) continue;

        const u32 sk = sb + 32768u + (u32)(tt & 1) * 32768u;

        float s[8][4];
        #pragma unroll
        for (int nt = 0; nt < 8; nt++)
            #pragma unroll
            for (int r = 0; r < 4; r++) s[nt][r] = 0.f;

        #pragma unroll
        for (int ks = 0; ks < 4; ks++) {
            u32 offA = (u32)((w*16 + lr)*128 + (ks*2 + lhi)*16);
            offA ^= (offA >> 3) & 0x70;
            u32 aqh[4], aql[4];
            ldsm4(aqh[0], aqh[1], aqh[2], aqh[3], sb + offA);
            ldsm4(aql[0], aql[1], aql[2], aql[3], sb + 16384 + offA);
            #pragma unroll
            for (int np = 0; np < 4; np++) {
                u32 offB = (u32)((np*16 + lr)*128 + (ks*2 + lhi)*16);
                offB ^= (offB >> 3) & 0x70;
                u32 bh[4], bl[4];
                ldsm4(bh[0], bh[1], bh[2], bh[3], sk + offB);
                ldsm4(bl[0], bl[1], bl[2], bl[3], sk + 8192 + offB);
                #pragma unroll
                for (int half = 0; half < 2; half++) {
                    const int nt = np*2 + half;
                    const u32 f0 = bh[half], f1 = bh[half+2];
                    mma16816(s[nt], aqh, f0, f1);
                    mma16816(s[nt], aql, f0, f1);
                    mma16816(s[nt], aqh, bl[half], bl[half+2]);
                }
            }
        }

        if (dcol + 63 > w*16) {
            #pragma unroll
            for (int nt = 0; nt < 8; nt++) {
                const int cc = nt*8 + cq + dcol;
                if (cc     > rg)     s[nt][0] = -INFINITY;
                if (cc + 1 > rg)     s[nt][1] = -INFINITY;
                if (cc     > rg + 8) s[nt][2] = -INFINITY;
                if (cc + 1 > rg + 8) s[nt][3] = -INFINITY;
            }
        }

        float rm0 = -INFINITY, rm1 = -INFINITY;
        #pragma unroll
        for (int nt = 0; nt < 8; nt++) {
            rm0 = fmaxf(rm0, fmaxf(s[nt][0], s[nt][1]));
            rm1 = fmaxf(rm1, fmaxf(s[nt][2], s[nt][3]));
        }
        rm0 = fmaxf(rm0, __shfl_xor_sync(0xffffffffu, rm0, 1));
        rm0 = fmaxf(rm0, __shfl_xor_sync(0xffffffffu, rm0, 2));
        rm1 = fmaxf(rm1, __shfl_xor_sync(0xffffffffu, rm1, 1));
        rm1 = fmaxf(rm1, __shfl_xor_sync(0xffffffffu, rm1, 2));
        float mn0 = fmaxf(m0, rm0), mn1 = fmaxf(m1, rm1);
        float alpha0 = __expf(0.125f * (m0 - mn0));
        float alpha1 = __expf(0.125f * (m1 - mn1));
        m0 = mn0; m1 = mn1;
        const float m08 = mn0 * 0.125f, m18 = mn1 * 0.125f;
        float rs0 = 0.f, rs1 = 0.f;
        #pragma unroll
        for (int nt = 0; nt < 8; nt++) {
            s[nt][0] = __expf(fmaf(s[nt][0], 0.125f, -m08));
            s[nt][1] = __expf(fmaf(s[nt][1], 0.125f, -m08));
            s[nt][2] = __expf(fmaf(s[nt][2], 0.125f, -m18));
            s[nt][3] = __expf(fmaf(s[nt][3], 0.125f, -m18));
            rs0 += s[nt][0] + s[nt][1];
            rs1 += s[nt][2] + s[nt][3];
        }
        rs0 += __shfl_xor_sync(0xffffffffu, rs0, 1);
        rs0 += __shfl_xor_sync(0xffffffffu, rs0, 2);
        rs1 += __shfl_xor_sync(0xffffffffu, rs1, 1);
        rs1 += __shfl_xor_sync(0xffffffffu, rs1, 2);
        l0 = l0 * alpha0 + rs0;
        l1 = l1 * alpha1 + rs1;
        #pragma unroll
        for (int nt = 0; nt < 8; nt++) {
            o[nt][0] *= alpha0; o[nt][1] *= alpha0;
            o[nt][2] *= alpha1; o[nt][3] *= alpha1;
        }

        #pragma unroll
        for (int kt = 0; kt < 4; kt++) {
            u32 aph[4], apl[4];
            #pragma unroll
            for (int half = 0; half < 2; half++) {
                const float plo0 = s[2*kt + half][0], phi0 = s[2*kt + half][1];
                const float plo1 = s[2*kt + half][2], phi1 = s[2*kt + half][3];
                u32 h0 = pkbf(phi0, plo0);
                u32 h1 = pkbf(phi1, plo1);
                aph[0 + 2*half] = h0;
                aph[1 + 2*half] = h1;
                apl[0 + 2*half] = pkbf(phi0 - bf_hi(h0), plo0 - bf_lo(h0));
                apl[1 + 2*half] = pkbf(phi1 - bf_hi(h1), plo1 - bf_lo(h1));
            }
            #pragma unroll
            for (int ng2 = 0; ng2 < 4; ng2++) {
                u32 offV = (u32)((kt*16 + lr)*128 + ng2*32 + lhi*16);
                offV ^= (offV >> 3) & 0x70;
                u32 v4h[4], v4l[4];
                ldsm4t(v4h[0], v4h[1], v4h[2], v4h[3], sk + 16384 + offV);
                ldsm4t(v4l[0], v4l[1], v4l[2], v4l[3], sk + 24576 + offV);
                const int nt = ng2 * 2;
                mma16816(o[nt],   aph, v4h[0], v4h[1]);
                mma16816(o[nt],   apl, v4h[0], v4h[1]);
                mma16816(o[nt],   aph, v4l[0], v4l[1]);
                mma16816(o[nt+1], aph, v4h[2], v4h[3]);
                mma16816(o[nt+1], apl, v4h[2], v4h[3]);
                mma16816(o[nt+1], aph, v4l[2], v4l[3]);
            }
        }
    }

    const float inv0 = 1.f / l0, inv1 = 1.f / l1;
    const size_t orow = (rowbase + q0 + rg) * D_ + colbase;
    #pragma unroll
    for (int nt = 0; nt < 8; nt++) {
        const int col = nt*8 + cq;
        float a0 = o[nt][0]*inv0, a1 = o[nt][1]*inv0;
        float a2 = o[nt][2]*inv1, a3 = o[nt][3]*inv1;
        u32 h01 = pkbf(a1, a0);
        u32 h23 = pkbf(a3, a2);
        u32 l01 = pkbf(a1 - bf_hi(h01), a0 - bf_lo(h01));
        u32 l23 = pkbf(a3 - bf_hi(h23), a2 - bf_lo(h23));
        *(u32*)(oh + orow + col)        = h01;
        *(u32*)(oh + orow + 8*D_ + col) = h23;
        *(u32*)(ol + orow + col)        = l01;
        *(u32*)(ol + orow + 8*D_ + col) = l23;
    }
}

// ---------------------------------------------------------------------------
extern "C" void kernel_launch(void* const* d_in, const int* in_sizes, int n_in,
                              void* d_out, int out_size)
{
    const float* q  = (const float*)d_in[0];
    const float* k  = (const float*)d_in[1];
    const float* v  = (const float*)d_in[2];
    const float* Wq = (const float*)d_in[3];
    const float* bq = (const float*)d_in[4];
    const float* Wk = (const float*)d_in[5];
    const float* bk = (const float*)d_in[6];
    const float* Wv = (const float*)d_in[7];
    const float* bv = (const float*)d_in[8];
    const float* Wo = (const float*)d_in[9];
    const float* bo = (const float*)d_in[10];
    float* out = (float*)d_out;

    __nv_bfloat16 *xh, *xl, *qhp, *qlp, *khp, *klp, *vhp, *vlp;
    cudaGetSymbolAddress((void**)&xh, g_xh);
    cudaGetSymbolAddress((void**)&xl, g_xl);
    cudaGetSymbolAddress((void**)&qhp, g_qh);
    cudaGetSymbolAddress((void**)&qlp, g_ql);
    cudaGetSymbolAddress((void**)&khp, g_kh);
    cudaGetSymbolAddress((void**)&klp, g_kl);
    cudaGetSymbolAddress((void**)&vhp, g_vh);
    cudaGetSymbolAddress((void**)&vlp, g_vl);

    cudaFuncSetAttribute(gemm_mma<1,1>,
                         cudaFuncAttributeMaxDynamicSharedMemorySize, GEMM_SMEM);
    cudaFuncSetAttribute(gemm_mma<0,0>,
                         cudaFuncAttributeMaxDynamicSharedMemorySize, GEMM_SMEM);
    cudaFuncSetAttribute(flash_attn_mma,
                         cudaFuncAttributeMaxDynamicSharedMemorySize, FA_SMEM);

    // fused Q/K/V projections: one launch, blockIdx.z selects projection
    GArgs gq = {};
    gq.A0[0] = q;  gq.A0[1] = k;  gq.A0[2] = v;
    gq.W[0] = Wq;  gq.W[1] = Wk;  gq.W[2] = Wv;
    gq.bias[0] = bq; gq.bias[1] = bk; gq.bias[2] = bv;
    gq.Ch[0] = qhp; gq.Ch[1] = khp; gq.Ch[2] = vhp;
    gq.Cl[0] = qlp; gq.Cl[1] = klp; gq.Cl[2] = vlp;
    gemm_mma<1,1><<<dim3(D_/128, M_/128, 3), 256, GEMM_SMEM>>>(gq);

    // attention (reads splits, writes bf16 hi/lo splits for O projection)
    flash_attn_mma<<<dim3(S_/128, B_*H_), 256, FA_SMEM>>>(qhp, qlp, khp, klp,
                                                           vhp, vlp, xh, xl);

    // output projection (A = pre-split bf16, W = fp32 in-kernel split, fp32 out)
    GArgs go = {};
    go.A0[0] = xh; go.A1[0] = xl;
    go.W[0] = Wo;  go.bias[0] = bo;
    go.Cf[0] = out;
    gemm_mma<0,0><<<dim3(D_/128, M_/128, 1), 256, GEMM_SMEM>>>(go);
}

// round 13
// speedup vs baseline: 2.9364x; 1.1865x over previous
#include <cuda_runtime.h>
#include <cuda_bf16.h>
#include <math.h>
#include <stdint.h>

#define B_  4
#define S_  2048
#define D_  1024
#define H_  16
#define DK_ 64
#define M_  (B_*S_)   // 8192

typedef unsigned long long u64;
typedef unsigned int u32;

// ===================== warp-level tensor-core helpers (non-"a" ISA) ========
__device__ __forceinline__ u32 smem_to_u32(const void* p) {
    u32 a;
    asm("{ .reg .u64 t; cvta.to.shared.u64 t, %1; cvt.u32.u64 %0, t; }"
        : "=r"(a) : "l"(p));
    return a;
}
__device__ __forceinline__ void ldsm4(u32& r0, u32& r1, u32& r2, u32& r3, u32 a) {
    asm volatile("ldmatrix.sync.aligned.m8n8.x4.shared.b16 {%0,%1,%2,%3}, [%4];"
                 : "=r"(r0), "=r"(r1), "=r"(r2), "=r"(r3) : "r"(a));
}
__device__ __forceinline__ void ldsm4t(u32& r0, u32& r1, u32& r2, u32& r3, u32 a) {
    asm volatile("ldmatrix.sync.aligned.m8n8.x4.trans.shared.b16 {%0,%1,%2,%3}, [%4];"
                 : "=r"(r0), "=r"(r1), "=r"(r2), "=r"(r3) : "r"(a));
}
__device__ __forceinline__ void mma16816(float* c, const u32* a, u32 b0, u32 b1) {
    asm volatile("mma.sync.aligned.m16n8k16.row.col.f32.bf16.bf16.f32 "
                 "{%0,%1,%2,%3}, {%4,%5,%6,%7}, {%8,%9}, {%0,%1,%2,%3};"
                 : "+f"(c[0]), "+f"(c[1]), "+f"(c[2]), "+f"(c[3])
                 : "r"(a[0]), "r"(a[1]), "r"(a[2]), "r"(a[3]), "r"(b0), "r"(b1));
}
// cvt.rn.bf16x2.f32 d, a, b  -> upper half = bf16(a), lower half = bf16(b)
__device__ __forceinline__ u32 pkbf(float hi, float lo) {
    u32 d;
    asm("cvt.rn.bf16x2.f32 %0, %1, %2;" : "=r"(d) : "f"(hi), "f"(lo));
    return d;
}
__device__ __forceinline__ float bf_lo(u32 v) { return __int_as_float((int)(v << 16)); }
__device__ __forceinline__ float bf_hi(u32 v) { return __int_as_float((int)(v & 0xffff0000u)); }

#define CP_ASYNC16(saddr, gptr) \
    asm volatile("cp.async.cg.shared.global [%0], [%1], 16;" \
                 :: "r"(saddr), "l"(gptr))
#define CP_COMMIT()  asm volatile("cp.async.commit_group;" ::: "memory")
#define CP_WAIT0()   asm volatile("cp.async.wait_group 0;" ::: "memory")

// ---------------- scratch (device globals: allocation-free) ----------------
__device__ __nv_bfloat16 g_ih[3][M_*D_];   // input splits (q,k,v) hi; [0] reused for attn out
__device__ __nv_bfloat16 g_il[3][M_*D_];   // input splits lo
__device__ __nv_bfloat16 g_wh[4][D_*D_];   // weight splits hi (Wq,Wk,Wv,Wo)
__device__ __nv_bfloat16 g_wl[4][D_*D_];   // weight splits lo
__device__ __nv_bfloat16 g_qh[M_*D_];
__device__ __nv_bfloat16 g_ql[M_*D_];
__device__ __nv_bfloat16 g_kh[M_*D_];
__device__ __nv_bfloat16 g_kl[M_*D_];
__device__ __nv_bfloat16 g_vh[M_*D_];
__device__ __nv_bfloat16 g_vl[M_*D_];

// ---------------------------------------------------------------------------
// one-launch split of all 7 fp32 tensors -> bf16 hi + lo
// ---------------------------------------------------------------------------
struct CArgs {
    const float* src[7];
    __nv_bfloat16* h[7];
    __nv_bfloat16* l[7];
    int n4[7];
};

__global__ __launch_bounds__(256)
void cvt_split7(CArgs ca)
{
    const int z = blockIdx.y;
    const int i = blockIdx.x * 256 + threadIdx.x;
    if (i >= ca.n4[z]) return;
    float4 v = ((const float4*)ca.src[z])[i];
    __nv_bfloat16 h0 = __float2bfloat16(v.x), h1 = __float2bfloat16(v.y);
    __nv_bfloat16 h2 = __float2bfloat16(v.z), h3 = __float2bfloat16(v.w);
    __nv_bfloat16 l0 = __float2bfloat16(v.x - __bfloat162float(h0));
    __nv_bfloat16 l1 = __float2bfloat16(v.y - __bfloat162float(h1));
    __nv_bfloat16 l2 = __float2bfloat16(v.z - __bfloat162float(h2));
    __nv_bfloat16 l3 = __float2bfloat16(v.w - __bfloat162float(h3));
    ((__nv_bfloat162*)ca.h[z])[2*i+0] = __nv_bfloat162(h0, h1);
    ((__nv_bfloat162*)ca.h[z])[2*i+1] = __nv_bfloat162(h2, h3);
    ((__nv_bfloat162*)ca.l[z])[2*i+0] = __nv_bfloat162(l0, l1);
    ((__nv_bfloat162*)ca.l[z])[2*i+1] = __nv_bfloat162(l2, l3);
}

// ---------------------------------------------------------------------------
// cp.async double-buffered mma.sync bf16x3 GEMM (all operands pre-split bf16):
//   C[z] = (Ah+Al)[z][M,K] @ (Wh+Wl)[z][N,K]^T + bias[z]
// CTA 128x128, K-chunk 64, 8 warps. smem = 2 x (Ah|Al|Wh|Wl) = 128 KB.
// ---------------------------------------------------------------------------
#define GEMM_SMEM (2*4*16384)   // 131072

struct GArgs2 {
    const __nv_bfloat16* Ah[3];
    const __nv_bfloat16* Al[3];
    const __nv_bfloat16* Wh[3];
    const __nv_bfloat16* Wl[3];
    const float* bias[3];
    __nv_bfloat16* Ch[3];
    __nv_bfloat16* Cl[3];
    float* Cf[3];
};

template<int OUT_SPLIT>
__global__ __launch_bounds__(256)
void gemm_mma(GArgs2 ga)
{
    extern __shared__ char smc[];
    const u32 sb   = smem_to_u32(smc);
    const int tid  = threadIdx.x, wid = tid >> 5, lane = tid & 31;
    const int z    = blockIdx.z;
    const int brow = blockIdx.y * 128, bcol = blockIdx.x * 128;
    const int wm   = wid & 1;
    const int wn   = wid >> 1;
    const int lr   = lane & 15, lhi = lane >> 4;

    const __nv_bfloat16* Ahg = ga.Ah[z];
    const __nv_bfloat16* Alg = ga.Al[z];
    const __nv_bfloat16* Whg = ga.Wh[z];
    const __nv_bfloat16* Wlg = ga.Wl[z];

    float acc[4][4][4];
    #pragma unroll
    for (int mt = 0; mt < 4; mt++)
        #pragma unroll
        for (int nt = 0; nt < 4; nt++)
            #pragma unroll
            for (int r = 0; r < 4; r++) acc[mt][nt][r] = 0.f;

    // async fill of one 64-KB chunk buffer (Ah|Al|Wh|Wl tiles)
    auto load_chunk = [&](int c, int bufb) {
        const int k0 = c * 64;
        const u32 base = sb + (u32)bufb * 65536u;
        #pragma unroll
        for (int seg = tid; seg < 1024; seg += 256) {
            int r = seg >> 3, s2 = seg & 7;
            u32 off = (u32)(r*128 + s2*16); off ^= (off >> 3) & 0x70;
            size_t ga_off = (size_t)(brow + r) * D_ + k0 + s2*8;
            size_t gw_off = (size_t)(bcol + r) * D_ + k0 + s2*8;
            CP_ASYNC16(base + off,          Ahg + ga_off);
            CP_ASYNC16(base + off + 16384,  Alg + ga_off);
            CP_ASYNC16(base + off + 32768,  Whg + gw_off);
            CP_ASYNC16(base + off + 49152,  Wlg + gw_off);
        }
        CP_COMMIT();
    };

    load_chunk(0, 0);

    for (int c = 0; c < 16; c++) {
        CP_WAIT0();
        __syncthreads();          // chunk c resident; all warps done with buf[(c+1)&1]
        if (c < 15) load_chunk(c + 1, (c + 1) & 1);

        const u32 sa = sb + (u32)(c & 1) * 65536u;

        #pragma unroll
        for (int ks = 0; ks < 4; ks++) {
            u32 ah[4][4], al[4][4];
            #pragma unroll
            for (int mt = 0; mt < 4; mt++) {
                int r = wm*64 + mt*16 + lr;
                u32 off = (u32)(r*128 + (ks*2 + lhi)*16);
                off ^= (off >> 3) & 0x70;
                ldsm4(ah[mt][0], ah[mt][1], ah[mt][2], ah[mt][3], sa + off);
                ldsm4(al[mt][0], al[mt][1], al[mt][2], al[mt][3], sa + 16384 + off);
            }
            #pragma unroll
            for (int np = 0; np < 2; np++) {
                int r = wn*32 + np*16 + lr;
                u32 off = (u32)(r*128 + (ks*2 + lhi)*16);
                off ^= (off >> 3) & 0x70;
                u32 bh[4], bl[4];
                ldsm4(bh[0], bh[1], bh[2], bh[3], sa + 32768 + off);
                ldsm4(bl[0], bl[1], bl[2], bl[3], sa + 49152 + off);
                #pragma unroll
                for (int half = 0; half < 2; half++) {
                    const int nt = np*2 + half;
                    const u32 fh0 = bh[half], fh1 = bh[half+2];
                    const u32 fl0 = bl[half], fl1 = bl[half+2];
                    #pragma unroll
                    for (int mt = 0; mt < 4; mt++) {
                        mma16816(acc[mt][nt], ah[mt], fh0, fh1);
                        mma16816(acc[mt][nt], al[mt], fh0, fh1);
                        mma16816(acc[mt][nt], ah[mt], fl0, fl1);
                    }
                }
            }
        }
    }

    const float* bias = ga.bias[z];
    const int r0 = lane >> 2, c0 = (lane & 3) * 2;
    #pragma unroll
    for (int nt = 0; nt < 4; nt++) {
        const int col = bcol + wn*32 + nt*8 + c0;
        float2 bv = *(const float2*)&bias[col];
        #pragma unroll
        for (int mt = 0; mt < 4; mt++) {
            const int row = brow + wm*64 + mt*16 + r0;
            float a0 = acc[mt][nt][0] + bv.x, a1 = acc[mt][nt][1] + bv.y;
            float a2 = acc[mt][nt][2] + bv.x, a3 = acc[mt][nt][3] + bv.y;
            if (OUT_SPLIT) {
                __nv_bfloat16* Ch = ga.Ch[z];
                __nv_bfloat16* Cl = ga.Cl[z];
                u32 h01 = pkbf(a1, a0);
                u32 h23 = pkbf(a3, a2);
                u32 l01 = pkbf(a1 - bf_hi(h01), a0 - bf_lo(h01));
                u32 l23 = pkbf(a3 - bf_hi(h23), a2 - bf_lo(h23));
                *(u32*)(Ch + (size_t)row     * D_ + col) = h01;
                *(u32*)(Ch + (size_t)(row+8) * D_ + col) = h23;
                *(u32*)(Cl + (size_t)row     * D_ + col) = l01;
                *(u32*)(Cl + (size_t)(row+8) * D_ + col) = l23;
            } else {
                float* Cf = ga.Cf[z];
                *(float2*)(Cf + (size_t)row     * D_ + col) = make_float2(a0, a1);
                *(float2*)(Cf + (size_t)(row+8) * D_ + col) = make_float2(a2, a3);
            }
        }
    }
}

// ---------------------------------------------------------------------------
// Causal flash attention, tensor cores, bf16x3 splits, fp32 softmax.
// Block = (b,h) x 128 q-rows, 8 warps. K/V 64-row tiles, cp.async
// double-buffered. Output written as bf16 hi/lo split.
// ---------------------------------------------------------------------------
#define FA_SMEM (32768 + 2*32768)   // 96 KB

__device__ __forceinline__ void fa_load_kv(char* dst,
    const __nv_bfloat16* __restrict__ kh, const __nv_bfloat16* __restrict__ kl,
    const __nv_bfloat16* __restrict__ vh, const __nv_bfloat16* __restrict__ vl,
    size_t gbase, int tid)
{
    #pragma unroll
    for (int seg = tid; seg < 512; seg += 256) {
        int r = seg >> 3, c = seg & 7;
        u32 off = (u32)(r*128 + c*16); off ^= (off >> 3) & 0x70;
        size_t g = gbase + (size_t)r * D_ + c*8;
        u32 s0 = smem_to_u32(dst + off);
        CP_ASYNC16(s0,         kh + g);
        CP_ASYNC16(s0 + 8192,  kl + g);
        CP_ASYNC16(s0 + 16384, vh + g);
        CP_ASYNC16(s0 + 24576, vl + g);
    }
    CP_COMMIT();
}

__global__ __launch_bounds__(256)
void flash_attn_mma(const __nv_bfloat16* __restrict__ qh, const __nv_bfloat16* __restrict__ ql,
                    const __nv_bfloat16* __restrict__ kh, const __nv_bfloat16* __restrict__ kl,
                    const __nv_bfloat16* __restrict__ vh, const __nv_bfloat16* __restrict__ vl,
                    __nv_bfloat16* __restrict__ oh, __nv_bfloat16* __restrict__ ol)
{
    extern __shared__ char smf[];
    const u32 sb = smem_to_u32(smf);
    const int tid = threadIdx.x, w = tid >> 5, lane = tid & 31;
    const int qb = (int)gridDim.x - 1 - (int)blockIdx.x;   // big tiles first
    const int q0 = qb * 128;
    const int b = blockIdx.y >> 4, h = blockIdx.y & 15;
    const size_t rowbase = (size_t)b * S_;
    const size_t colbase = (size_t)h * 64;

    const int lr = lane & 15, lhi = lane >> 4;
    const int r0 = lane >> 2, cq = (lane & 3) * 2;
    const int rg = w*16 + r0;

    {
        const __nv_bfloat16* gh = qh + (rowbase + q0) * D_ + colbase;
        const __nv_bfloat16* gl = ql + (rowbase + q0) * D_ + colbase;
        #pragma unroll
        for (int seg = tid; seg < 1024; seg += 256) {
            int r = seg >> 3, c = seg & 7;
            u32 off = (u32)(r*128 + c*16); off ^= (off >> 3) & 0x70;
            *(uint4*)(smf + off)         = *(const uint4*)(gh + (size_t)r * D_ + c*8);
            *(uint4*)(smf + 16384 + off) = *(const uint4*)(gl + (size_t)r * D_ + c*8);
        }
    }

    const int ttmax = 2*qb + 1;
    fa_load_kv(smf + 32768, kh, kl, vh, vl, rowbase * D_ + colbase, tid);

    float m0 = -INFINITY, m1 = -INFINITY, l0 = 0.f, l1 = 0.f;
    float o[8][4];
    #pragma unroll
    for (int nt = 0; nt < 8; nt++)
        #pragma unroll
        for (int r = 0; r < 4; r++) o[nt][r] = 0.f;

    for (int tt = 0; tt <= ttmax; tt++) {
        CP_WAIT0();
        __syncthreads();
        if (tt < ttmax)
            fa_load_kv(smf + 32768 + ((tt+1)&1)*32768, kh, kl, vh, vl,
                       (rowbase + (size_t)(tt+1)*64) * D_ + colbase, tid);

        const int dcol = tt*64 - q0;
        if (dcol > w*16 + 15) continue;

        const u32 sk = sb + 32768u + (u32)(tt & 1) * 32768u;

        float s[8][4];
        #pragma unroll
        for (int nt = 0; nt < 8; nt++)
            #pragma unroll
            for (int r = 0; r < 4; r++) s[nt][r] = 0.f;

        #pragma unroll
        for (int ks = 0; ks < 4; ks++) {
            u32 offA = (u32)((w*16 + lr)*128 + (ks*2 + lhi)*16);
            offA ^= (offA >> 3) & 0x70;
            u32 aqh[4], aql[4];
            ldsm4(aqh[0], aqh[1], aqh[2], aqh[3], sb + offA);
            ldsm4(aql[0], aql[1], aql[2], aql[3], sb + 16384 + offA);
            #pragma unroll
            for (int np = 0; np < 4; np++) {
                u32 offB = (u32)((np*16 + lr)*128 + (ks*2 + lhi)*16);
                offB ^= (offB >> 3) & 0x70;
                u32 bh[4], bl[4];
                ldsm4(bh[0], bh[1], bh[2], bh[3], sk + offB);
                ldsm4(bl[0], bl[1], bl[2], bl[3], sk + 8192 + offB);
                #pragma unroll
                for (int half = 0; half < 2; half++) {
                    const int nt = np*2 + half;
                    const u32 f0 = bh[half], f1 = bh[half+2];
                    mma16816(s[nt], aqh, f0, f1);
                    mma16816(s[nt], aql, f0, f1);
                    mma16816(s[nt], aqh, bl[half], bl[half+2]);
                }
            }
        }

        if (dcol + 63 > w*16) {
            #pragma unroll
            for (int nt = 0; nt < 8; nt++) {
                const int cc = nt*8 + cq + dcol;
                if (cc     > rg)     s[nt][0] = -INFINITY;
                if (cc + 1 > rg)     s[nt][1] = -INFINITY;
                if (cc     > rg + 8) s[nt][2] = -INFINITY;
                if (cc + 1 > rg + 8) s[nt][3] = -INFINITY;
            }
        }

        float rm0 = -INFINITY, rm1 = -INFINITY;
        #pragma unroll
        for (int nt = 0; nt < 8; nt++) {
            rm0 = fmaxf(rm0, fmaxf(s[nt][0], s[nt][1]));
            rm1 = fmaxf(rm1, fmaxf(s[nt][2], s[nt][3]));
        }
        rm0 = fmaxf(rm0, __shfl_xor_sync(0xffffffffu, rm0, 1));
        rm0 = fmaxf(rm0, __shfl_xor_sync(0xffffffffu, rm0, 2));
        rm1 = fmaxf(rm1, __shfl_xor_sync(0xffffffffu, rm1, 1));
        rm1 = fmaxf(rm1, __shfl_xor_sync(0xffffffffu, rm1, 2));
        float mn0 = fmaxf(m0, rm0), mn1 = fmaxf(m1, rm1);
        float alpha0 = __expf(0.125f * (m0 - mn0));
        float alpha1 = __expf(0.125f * (m1 - mn1));
        m0 = mn0; m1 = mn1;
        const float m08 = mn0 * 0.125f, m18 = mn1 * 0.125f;
        float rs0 = 0.f, rs1 = 0.f;
        #pragma unroll
        for (int nt = 0; nt < 8; nt++) {
            s[nt][0] = __expf(fmaf(s[nt][0], 0.125f, -m08));
            s[nt][1] = __expf(fmaf(s[nt][1], 0.125f, -m08));
            s[nt][2] = __expf(fmaf(s[nt][2], 0.125f, -m18));
            s[nt][3] = __expf(fmaf(s[nt][3], 0.125f, -m18));
            rs0 += s[nt][0] + s[nt][1];
            rs1 += s[nt][2] + s[nt][3];
        }
        rs0 += __shfl_xor_sync(0xffffffffu, rs0, 1);
        rs0 += __shfl_xor_sync(0xffffffffu, rs0, 2);
        rs1 += __shfl_xor_sync(0xffffffffu, rs1, 1);
        rs1 += __shfl_xor_sync(0xffffffffu, rs1, 2);
        l0 = l0 * alpha0 + rs0;
        l1 = l1 * alpha1 + rs1;
        #pragma unroll
        for (int nt = 0; nt < 8; nt++) {
            o[nt][0] *= alpha0; o[nt][1] *= alpha0;
            o[nt][2] *= alpha1; o[nt][3] *= alpha1;
        }

        #pragma unroll
        for (int kt = 0; kt < 4; kt++) {
            u32 aph[4], apl[4];
            #pragma unroll
            for (int half = 0; half < 2; half++) {
                const float plo0 = s[2*kt + half][0], phi0 = s[2*kt + half][1];
                const float plo1 = s[2*kt + half][2], phi1 = s[2*kt + half][3];
                u32 h0 = pkbf(phi0, plo0);
                u32 h1 = pkbf(phi1, plo1);
                aph[0 + 2*half] = h0;
                aph[1 + 2*half] = h1;
                apl[0 + 2*half] = pkbf(phi0 - bf_hi(h0), plo0 - bf_lo(h0));
                apl[1 + 2*half] = pkbf(phi1 - bf_hi(h1), plo1 - bf_lo(h1));
            }
            #pragma unroll
            for (int ng2 = 0; ng2 < 4; ng2++) {
                u32 offV = (u32)((kt*16 + lr)*128 + ng2*32 + lhi*16);
                offV ^= (offV >> 3) & 0x70;
                u32 v4h[4], v4l[4];
                ldsm4t(v4h[0], v4h[1], v4h[2], v4h[3], sk + 16384 + offV);
                ldsm4t(v4l[0], v4l[1], v4l[2], v4l[3], sk + 24576 + offV);
                const int nt = ng2 * 2;
                mma16816(o[nt],   aph, v4h[0], v4h[1]);
                mma16816(o[nt],   apl, v4h[0], v4h[1]);
                mma16816(o[nt],   aph, v4l[0], v4l[1]);
                mma16816(o[nt+1], aph, v4h[2], v4h[3]);
                mma16816(o[nt+1], apl, v4h[2], v4h[3]);
                mma16816(o[nt+1], aph, v4l[2], v4l[3]);
            }
        }
    }

    const float inv0 = 1.f / l0, inv1 = 1.f / l1;
    const size_t orow = (rowbase + q0 + rg) * D_ + colbase;
    #pragma unroll
    for (int nt = 0; nt < 8; nt++) {
        const int col = nt*8 + cq;
        float a0 = o[nt][0]*inv0, a1 = o[nt][1]*inv0;
        float a2 = o[nt][2]*inv1, a3 = o[nt][3]*inv1;
        u32 h01 = pkbf(a1, a0);
        u32 h23 = pkbf(a3, a2);
        u32 l01 = pkbf(a1 - bf_hi(h01), a0 - bf_lo(h01));
        u32 l23 = pkbf(a3 - bf_hi(h23), a2 - bf_lo(h23));
        *(u32*)(oh + orow + col)        = h01;
        *(u32*)(oh + orow + 8*D_ + col) = h23;
        *(u32*)(ol + orow + col)        = l01;
        *(u32*)(ol + orow + 8*D_ + col) = l23;
    }
}

// ---------------------------------------------------------------------------
extern "C" void kernel_launch(void* const* d_in, const int* in_sizes, int n_in,
                              void* d_out, int out_size)
{
    const float* q  = (const float*)d_in[0];
    const float* k  = (const float*)d_in[1];
    const float* v  = (const float*)d_in[2];
    const float* Wq = (const float*)d_in[3];
    const float* bq = (const float*)d_in[4];
    const float* Wk = (const float*)d_in[5];
    const float* bk = (const float*)d_in[6];
    const float* Wv = (const float*)d_in[7];
    const float* bv = (const float*)d_in[8];
    const float* Wo = (const float*)d_in[9];
    const float* bo = (const float*)d_in[10];
    float* out = (float*)d_out;

    __nv_bfloat16 *ih, *il, *wh, *wl, *qhp, *qlp, *khp, *klp, *vhp, *vlp;
    cudaGetSymbolAddress((void**)&ih, g_ih);
    cudaGetSymbolAddress((void**)&il, g_il);
    cudaGetSymbolAddress((void**)&wh, g_wh);
    cudaGetSymbolAddress((void**)&wl, g_wl);
    cudaGetSymbolAddress((void**)&qhp, g_qh);
    cudaGetSymbolAddress((void**)&qlp, g_ql);
    cudaGetSymbolAddress((void**)&khp, g_kh);
    cudaGetSymbolAddress((void**)&klp, g_kl);
    cudaGetSymbolAddress((void**)&vhp, g_vh);
    cudaGetSymbolAddress((void**)&vlp, g_vl);

    const size_t NX = (size_t)M_ * D_;
    const size_t NW = (size_t)D_ * D_;

    cudaFuncSetAttribute(gemm_mma<1>,
                         cudaFuncAttributeMaxDynamicSharedMemorySize, GEMM_SMEM);
    cudaFuncSetAttribute(gemm_mma<0>,
                         cudaFuncAttributeMaxDynamicSharedMemorySize, GEMM_SMEM);
    cudaFuncSetAttribute(flash_attn_mma,
                         cudaFuncAttributeMaxDynamicSharedMemorySize, FA_SMEM);

    // one launch: split q,k,v + all 4 weights into bf16 hi/lo
    CArgs ca = {};
    ca.src[0] = q;  ca.h[0] = ih;        ca.l[0] = il;        ca.n4[0] = (int)(NX/4);
    ca.src[1] = k;  ca.h[1] = ih + NX;   ca.l[1] = il + NX;   ca.n4[1] = (int)(NX/4);
    ca.src[2] = v;  ca.h[2] = ih + 2*NX; ca.l[2] = il + 2*NX; ca.n4[2] = (int)(NX/4);
    ca.src[3] = Wq; ca.h[3] = wh;        ca.l[3] = wl;        ca.n4[3] = (int)(NW/4);
    ca.src[4] = Wk; ca.h[4] = wh + NW;   ca.l[4] = wl + NW;   ca.n4[4] = (int)(NW/4);
    ca.src[5] = Wv; ca.h[5] = wh + 2*NW; ca.l[5] = wl + 2*NW; ca.n4[5] = (int)(NW/4);
    ca.src[6] = Wo; ca.h[6] = wh + 3*NW; ca.l[6] = wl + 3*NW; ca.n4[6] = (int)(NW/4);
    cvt_split7<<<dim3((unsigned)(NX/4/256), 7), 256>>>(ca);

    // fused Q/K/V projections, cp.async double-buffered
    GArgs2 gq = {};
    gq.Ah[0] = ih;        gq.Al[0] = il;        gq.Wh[0] = wh;        gq.Wl[0] = wl;
    gq.Ah[1] = ih + NX;   gq.Al[1] = il + NX;   gq.Wh[1] = wh + NW;   gq.Wl[1] = wl + NW;
    gq.Ah[2] = ih + 2*NX; gq.Al[2] = il + 2*NX; gq.Wh[2] = wh + 2*NW; gq.Wl[2] = wl + 2*NW;
    gq.bias[0] = bq; gq.bias[1] = bk; gq.bias[2] = bv;
    gq.Ch[0] = qhp; gq.Ch[1] = khp; gq.Ch[2] = vhp;
    gq.Cl[0] = qlp; gq.Cl[1] = klp; gq.Cl[2] = vlp;
    gemm_mma<1><<<dim3(D_/128, M_/128, 3), 256, GEMM_SMEM>>>(gq);

    // attention: writes bf16 hi/lo splits into the (now free) q-input buffers
    flash_attn_mma<<<dim3(S_/128, B_*H_), 256, FA_SMEM>>>(qhp, qlp, khp, klp,
                                                           vhp, vlp, ih, il);

    // output projection (fp32 out)
    GArgs2 go = {};
    go.Ah[0] = ih; go.Al[0] = il;
    go.Wh[0] = wh + 3*NW; go.Wl[0] = wl + 3*NW;
    go.bias[0] = bo;
    go.Cf[0] = out;
    gemm_mma<0><<<dim3(D_/128, M_/128, 1), 256, GEMM_SMEM>>>(go);
}

// round 14
// speedup vs baseline: 2.9545x; 1.0062x over previous
#include <cuda_runtime.h>
#include <cuda_bf16.h>
#include <math.h>
#include <stdint.h>

#define B_  4
#define S_  2048
#define D_  1024
#define H_  16
#define DK_ 64
#define M_  (B_*S_)   // 8192

typedef unsigned long long u64;
typedef unsigned int u32;

// ===================== warp-level tensor-core helpers (non-"a" ISA) ========
__device__ __forceinline__ u32 smem_to_u32(const void* p) {
    u32 a;
    asm("{ .reg .u64 t; cvta.to.shared.u64 t, %1; cvt.u32.u64 %0, t; }"
        : "=r"(a) : "l"(p));
    return a;
}
__device__ __forceinline__ void ldsm4(u32& r0, u32& r1, u32& r2, u32& r3, u32 a) {
    asm volatile("ldmatrix.sync.aligned.m8n8.x4.shared.b16 {%0,%1,%2,%3}, [%4];"
                 : "=r"(r0), "=r"(r1), "=r"(r2), "=r"(r3) : "r"(a));
}
__device__ __forceinline__ void ldsm4t(u32& r0, u32& r1, u32& r2, u32& r3, u32 a) {
    asm volatile("ldmatrix.sync.aligned.m8n8.x4.trans.shared.b16 {%0,%1,%2,%3}, [%4];"
                 : "=r"(r0), "=r"(r1), "=r"(r2), "=r"(r3) : "r"(a));
}
__device__ __forceinline__ void mma16816(float* c, const u32* a, u32 b0, u32 b1) {
    asm volatile("mma.sync.aligned.m16n8k16.row.col.f32.bf16.bf16.f32 "
                 "{%0,%1,%2,%3}, {%4,%5,%6,%7}, {%8,%9}, {%0,%1,%2,%3};"
                 : "+f"(c[0]), "+f"(c[1]), "+f"(c[2]), "+f"(c[3])
                 : "r"(a[0]), "r"(a[1]), "r"(a[2]), "r"(a[3]), "r"(b0), "r"(b1));
}
// cvt.rn.bf16x2.f32 d, a, b  -> upper half = bf16(a), lower half = bf16(b)
__device__ __forceinline__ u32 pkbf(float hi, float lo) {
    u32 d;
    asm("cvt.rn.bf16x2.f32 %0, %1, %2;" : "=r"(d) : "f"(hi), "f"(lo));
    return d;
}
__device__ __forceinline__ float bf_lo(u32 v) { return __int_as_float((int)(v << 16)); }
__device__ __forceinline__ float bf_hi(u32 v) { return __int_as_float((int)(v & 0xffff0000u)); }

#define CP_ASYNC16(saddr, gptr) \
    asm volatile("cp.async.cg.shared.global [%0], [%1], 16;" \
                 :: "r"(saddr), "l"(gptr))
#define CP_COMMIT()  asm volatile("cp.async.commit_group;" ::: "memory")
#define CP_WAIT0()   asm volatile("cp.async.wait_group 0;" ::: "memory")

// ---------------- scratch (device globals: allocation-free) ----------------
__device__ __nv_bfloat16 g_ih[3][M_*D_];   // input splits (q,k,v) hi; [0] reused for attn out
__device__ __nv_bfloat16 g_il[3][M_*D_];   // input splits lo
__device__ __nv_bfloat16 g_wh[4][D_*D_];   // weight splits hi (Wq,Wk,Wv,Wo)
__device__ __nv_bfloat16 g_wl[4][D_*D_];   // weight splits lo
__device__ __nv_bfloat16 g_qh[M_*D_];
__device__ __nv_bfloat16 g_ql[M_*D_];
__device__ __nv_bfloat16 g_kh[M_*D_];
__device__ __nv_bfloat16 g_kl[M_*D_];
__device__ __nv_bfloat16 g_vh[M_*D_];
__device__ __nv_bfloat16 g_vl[M_*D_];

// ---------------------------------------------------------------------------
// one-launch split of all 7 fp32 tensors -> bf16 hi + lo
// ---------------------------------------------------------------------------
struct CArgs {
    const float* src[7];
    __nv_bfloat16* h[7];
    __nv_bfloat16* l[7];
    int n4[7];
};

__global__ __launch_bounds__(256)
void cvt_split7(CArgs ca)
{
    const int z = blockIdx.y;
    const int i = blockIdx.x * 256 + threadIdx.x;
    if (i >= ca.n4[z]) return;
    float4 v = ((const float4*)ca.src[z])[i];
    __nv_bfloat16 h0 = __float2bfloat16(v.x), h1 = __float2bfloat16(v.y);
    __nv_bfloat16 h2 = __float2bfloat16(v.z), h3 = __float2bfloat16(v.w);
    __nv_bfloat16 l0 = __float2bfloat16(v.x - __bfloat162float(h0));
    __nv_bfloat16 l1 = __float2bfloat16(v.y - __bfloat162float(h1));
    __nv_bfloat16 l2 = __float2bfloat16(v.z - __bfloat162float(h2));
    __nv_bfloat16 l3 = __float2bfloat16(v.w - __bfloat162float(h3));
    ((__nv_bfloat162*)ca.h[z])[2*i+0] = __nv_bfloat162(h0, h1);
    ((__nv_bfloat162*)ca.h[z])[2*i+1] = __nv_bfloat162(h2, h3);
    ((__nv_bfloat162*)ca.l[z])[2*i+0] = __nv_bfloat162(l0, l1);
    ((__nv_bfloat162*)ca.l[z])[2*i+1] = __nv_bfloat162(l2, l3);
}

// ---------------------------------------------------------------------------
// cp.async double-buffered mma.sync bf16x3 GEMM (all operands pre-split bf16):
//   C[z] = (Ah+Al)[z][M,K] @ (Wh+Wl)[z][N,K]^T + bias[z]
// CTA 128x128, K-chunk 64, 8 warps. smem = 2 x (Ah|Al|Wh|Wl) = 128 KB.
// MMA phase is TERM-MAJOR: all hh MMAs, then lh, then hl -> accumulator
// reuse distance 16 (covers HMMA latency at 2 warps/SMSP).
// ---------------------------------------------------------------------------
#define GEMM_SMEM (2*4*16384)   // 131072

struct GArgs2 {
    const __nv_bfloat16* Ah[3];
    const __nv_bfloat16* Al[3];
    const __nv_bfloat16* Wh[3];
    const __nv_bfloat16* Wl[3];
    const float* bias[3];
    __nv_bfloat16* Ch[3];
    __nv_bfloat16* Cl[3];
    float* Cf[3];
};

template<int OUT_SPLIT>
__global__ __launch_bounds__(256)
void gemm_mma(GArgs2 ga)
{
    extern __shared__ char smc[];
    const u32 sb   = smem_to_u32(smc);
    const int tid  = threadIdx.x, wid = tid >> 5, lane = tid & 31;
    const int z    = blockIdx.z;
    const int brow = blockIdx.y * 128, bcol = blockIdx.x * 128;
    const int wm   = wid & 1;
    const int wn   = wid >> 1;
    const int lr   = lane & 15, lhi = lane >> 4;

    const __nv_bfloat16* Ahg = ga.Ah[z];
    const __nv_bfloat16* Alg = ga.Al[z];
    const __nv_bfloat16* Whg = ga.Wh[z];
    const __nv_bfloat16* Wlg = ga.Wl[z];

    float acc[4][4][4];
    #pragma unroll
    for (int mt = 0; mt < 4; mt++)
        #pragma unroll
        for (int nt = 0; nt < 4; nt++)
            #pragma unroll
            for (int r = 0; r < 4; r++) acc[mt][nt][r] = 0.f;

    auto load_chunk = [&](int c, int bufb) {
        const int k0 = c * 64;
        const u32 base = sb + (u32)bufb * 65536u;
        #pragma unroll
        for (int seg = tid; seg < 1024; seg += 256) {
            int r = seg >> 3, s2 = seg & 7;
            u32 off = (u32)(r*128 + s2*16); off ^= (off >> 3) & 0x70;
            size_t ga_off = (size_t)(brow + r) * D_ + k0 + s2*8;
            size_t gw_off = (size_t)(bcol + r) * D_ + k0 + s2*8;
            CP_ASYNC16(base + off,          Ahg + ga_off);
            CP_ASYNC16(base + off + 16384,  Alg + ga_off);
            CP_ASYNC16(base + off + 32768,  Whg + gw_off);
            CP_ASYNC16(base + off + 49152,  Wlg + gw_off);
        }
        CP_COMMIT();
    };

    load_chunk(0, 0);

    for (int c = 0; c < 16; c++) {
        CP_WAIT0();
        __syncthreads();
        if (c < 15) load_chunk(c + 1, (c + 1) & 1);

        const u32 sa = sb + (u32)(c & 1) * 65536u;

        #pragma unroll
        for (int ks = 0; ks < 4; ks++) {
            u32 ah[4][4], al[4][4];
            #pragma unroll
            for (int mt = 0; mt < 4; mt++) {
                int r = wm*64 + mt*16 + lr;
                u32 off = (u32)(r*128 + (ks*2 + lhi)*16);
                off ^= (off >> 3) & 0x70;
                ldsm4(ah[mt][0], ah[mt][1], ah[mt][2], ah[mt][3], sa + off);
                ldsm4(al[mt][0], al[mt][1], al[mt][2], al[mt][3], sa + 16384 + off);
            }
            u32 bh[2][4], bl[2][4];
            #pragma unroll
            for (int np = 0; np < 2; np++) {
                int r = wn*32 + np*16 + lr;
                u32 off = (u32)(r*128 + (ks*2 + lhi)*16);
                off ^= (off >> 3) & 0x70;
                ldsm4(bh[np][0], bh[np][1], bh[np][2], bh[np][3], sa + 32768 + off);
                ldsm4(bl[np][0], bl[np][1], bl[np][2], bl[np][3], sa + 49152 + off);
            }
            // term 1: Ah * Bh   (16 independent MMAs)
            #pragma unroll
            for (int np = 0; np < 2; np++)
                #pragma unroll
                for (int half = 0; half < 2; half++) {
                    const int nt = np*2 + half;
                    #pragma unroll
                    for (int mt = 0; mt < 4; mt++)
                        mma16816(acc[mt][nt], ah[mt], bh[np][half], bh[np][half+2]);
                }
            // term 2: Al * Bh
            #pragma unroll
            for (int np = 0; np < 2; np++)
                #pragma unroll
                for (int half = 0; half < 2; half++) {
                    const int nt = np*2 + half;
                    #pragma unroll
                    for (int mt = 0; mt < 4; mt++)
                        mma16816(acc[mt][nt], al[mt], bh[np][half], bh[np][half+2]);
                }
            // term 3: Ah * Bl
            #pragma unroll
            for (int np = 0; np < 2; np++)
                #pragma unroll
                for (int half = 0; half < 2; half++) {
                    const int nt = np*2 + half;
                    #pragma unroll
                    for (int mt = 0; mt < 4; mt++)
                        mma16816(acc[mt][nt], ah[mt], bl[np][half], bl[np][half+2]);
                }
        }
    }

    const float* bias = ga.bias[z];
    const int r0 = lane >> 2, c0 = (lane & 3) * 2;
    #pragma unroll
    for (int nt = 0; nt < 4; nt++) {
        const int col = bcol + wn*32 + nt*8 + c0;
        float2 bv = *(const float2*)&bias[col];
        #pragma unroll
        for (int mt = 0; mt < 4; mt++) {
            const int row = brow + wm*64 + mt*16 + r0;
            float a0 = acc[mt][nt][0] + bv.x, a1 = acc[mt][nt][1] + bv.y;
            float a2 = acc[mt][nt][2] + bv.x, a3 = acc[mt][nt][3] + bv.y;
            if (OUT_SPLIT) {
                __nv_bfloat16* Ch = ga.Ch[z];
                __nv_bfloat16* Cl = ga.Cl[z];
                u32 h01 = pkbf(a1, a0);
                u32 h23 = pkbf(a3, a2);
                u32 l01 = pkbf(a1 - bf_hi(h01), a0 - bf_lo(h01));
                u32 l23 = pkbf(a3 - bf_hi(h23), a2 - bf_lo(h23));
                *(u32*)(Ch + (size_t)row     * D_ + col) = h01;
                *(u32*)(Ch + (size_t)(row+8) * D_ + col) = h23;
                *(u32*)(Cl + (size_t)row     * D_ + col) = l01;
                *(u32*)(Cl + (size_t)(row+8) * D_ + col) = l23;
            } else {
                float* Cf = ga.Cf[z];
                *(float2*)(Cf + (size_t)row     * D_ + col) = make_float2(a0, a1);
                *(float2*)(Cf + (size_t)(row+8) * D_ + col) = make_float2(a2, a3);
            }
        }
    }
}

// ---------------------------------------------------------------------------
// Causal flash attention, tensor cores, bf16x3 splits, fp32 softmax.
// Block = (b,h) x 128 q-rows, 8 warps. K/V 64-row tiles, cp.async
// double-buffered. Term-major MMA ordering (reuse distance 8).
// ---------------------------------------------------------------------------
#define FA_SMEM (32768 + 2*32768)   // 96 KB

__device__ __forceinline__ void fa_load_kv(char* dst,
    const __nv_bfloat16* __restrict__ kh, const __nv_bfloat16* __restrict__ kl,
    const __nv_bfloat16* __restrict__ vh, const __nv_bfloat16* __restrict__ vl,
    size_t gbase, int tid)
{
    #pragma unroll
    for (int seg = tid; seg < 512; seg += 256) {
        int r = seg >> 3, c = seg & 7;
        u32 off = (u32)(r*128 + c*16); off ^= (off >> 3) & 0x70;
        size_t g = gbase + (size_t)r * D_ + c*8;
        u32 s0 = smem_to_u32(dst + off);
        CP_ASYNC16(s0,         kh + g);
        CP_ASYNC16(s0 + 8192,  kl + g);
        CP_ASYNC16(s0 + 16384, vh + g);
        CP_ASYNC16(s0 + 24576, vl + g);
    }
    CP_COMMIT();
}

__global__ __launch_bounds__(256)
void flash_attn_mma(const __nv_bfloat16* __restrict__ qh, const __nv_bfloat16* __restrict__ ql,
                    const __nv_bfloat16* __restrict__ kh, const __nv_bfloat16* __restrict__ kl,
                    const __nv_bfloat16* __restrict__ vh, const __nv_bfloat16* __restrict__ vl,
                    __nv_bfloat16* __restrict__ oh, __nv_bfloat16* __restrict__ ol)
{
    extern __shared__ char smf[];
    const u32 sb = smem_to_u32(smf);
    const int tid = threadIdx.x, w = tid >> 5, lane = tid & 31;
    const int qb = (int)gridDim.x - 1 - (int)blockIdx.x;   // big tiles first
    const int q0 = qb * 128;
    const int b = blockIdx.y >> 4, h = blockIdx.y & 15;
    const size_t rowbase = (size_t)b * S_;
    const size_t colbase = (size_t)h * 64;

    const int lr = lane & 15, lhi = lane >> 4;
    const int r0 = lane >> 2, cq = (lane & 3) * 2;
    const int rg = w*16 + r0;

    {
        const __nv_bfloat16* gh = qh + (rowbase + q0) * D_ + colbase;
        const __nv_bfloat16* gl = ql + (rowbase + q0) * D_ + colbase;
        #pragma unroll
        for (int seg = tid; seg < 1024; seg += 256) {
            int r = seg >> 3, c = seg & 7;
            u32 off = (u32)(r*128 + c*16); off ^= (off >> 3) & 0x70;
            *(uint4*)(smf + off)         = *(const uint4*)(gh + (size_t)r * D_ + c*8);
            *(uint4*)(smf + 16384 + off) = *(const uint4*)(gl + (size_t)r * D_ + c*8);
        }
    }

    const int ttmax = 2*qb + 1;
    fa_load_kv(smf + 32768, kh, kl, vh, vl, rowbase * D_ + colbase, tid);

    float m0 = -INFINITY, m1 = -INFINITY, l0 = 0.f, l1 = 0.f;
    float o[8][4];
    #pragma unroll
    for (int nt = 0; nt < 8; nt++)
        #pragma unroll
        for (int r = 0; r < 4; r++) o[nt][r] = 0.f;

    for (int tt = 0; tt <= ttmax; tt++) {
        CP_WAIT0();
        __syncthreads();
        if (tt < ttmax)
            fa_load_kv(smf + 32768 + ((tt+1)&1)*32768, kh, kl, vh, vl,
                       (rowbase + (size_t)(tt+1)*64) * D_ + colbase, tid);

        const int dcol = tt*64 - q0;
        if (dcol > w*16 + 15) continue;

        const u32 sk = sb + 32768u + (u32)(tt & 1) * 32768u;

        float s[8][4];
        #pragma unroll
        for (int nt = 0; nt < 8; nt++)
            #pragma unroll
            for (int r = 0; r < 4; r++) s[nt][r] = 0.f;

        #pragma unroll
        for (int ks = 0; ks < 4; ks++) {
            u32 offA = (u32)((w*16 + lr)*128 + (ks*2 + lhi)*16);
            offA ^= (offA >> 3) & 0x70;
            u32 aqh[4], aql[4];
            ldsm4(aqh[0], aqh[1], aqh[2], aqh[3], sb + offA);
            ldsm4(aql[0], aql[1], aql[2], aql[3], sb + 16384 + offA);
            u32 bh[4][4], bl[4][4];
            #pragma unroll
            for (int np = 0; np < 4; np++) {
                u32 offB = (u32)((np*16 + lr)*128 + (ks*2 + lhi)*16);
                offB ^= (offB >> 3) & 0x70;
                ldsm4(bh[np][0], bh[np][1], bh[np][2], bh[np][3], sk + offB);
                ldsm4(bl[np][0], bl[np][1], bl[np][2], bl[np][3], sk + 8192 + offB);
            }
            // term 1: Qh * Kh (8 independent MMAs)
            #pragma unroll
            for (int np = 0; np < 4; np++)
                #pragma unroll
                for (int half = 0; half < 2; half++)
                    mma16816(s[np*2 + half], aqh, bh[np][half], bh[np][half+2]);
            // term 2: Ql * Kh
            #pragma unroll
            for (int np = 0; np < 4; np++)
                #pragma unroll
                for (int half = 0; half < 2; half++)
                    mma16816(s[np*2 + half], aql, bh[np][half], bh[np][half+2]);
            // term 3: Qh * Kl
            #pragma unroll
            for (int np = 0; np < 4; np++)
                #pragma unroll
                for (int half = 0; half < 2; half++)
                    mma16816(s[np*2 + half], aqh, bl[np][half], bl[np][half+2]);
        }

        if (dcol + 63 > w*16) {
            #pragma unroll
            for (int nt = 0; nt < 8; nt++) {
                const int cc = nt*8 + cq + dcol;
                if (cc     > rg)     s[nt][0] = -INFINITY;
                if (cc + 1 > rg)     s[nt][1] = -INFINITY;
                if (cc     > rg + 8) s[nt][2] = -INFINITY;
                if (cc + 1 > rg + 8) s[nt][3] = -INFINITY;
            }
        }

        float rm0 = -INFINITY, rm1 = -INFINITY;
        #pragma unroll
        for (int nt = 0; nt < 8; nt++) {
            rm0 = fmaxf(rm0, fmaxf(s[nt][0], s[nt][1]));
            rm1 = fmaxf(rm1, fmaxf(s[nt][2], s[nt][3]));
        }
        rm0 = fmaxf(rm0, __shfl_xor_sync(0xffffffffu, rm0, 1));
        rm0 = fmaxf(rm0, __shfl_xor_sync(0xffffffffu, rm0, 2));
        rm1 = fmaxf(rm1, __shfl_xor_sync(0xffffffffu, rm1, 1));
        rm1 = fmaxf(rm1, __shfl_xor_sync(0xffffffffu, rm1, 2));
        float mn0 = fmaxf(m0, rm0), mn1 = fmaxf(m1, rm1);
        float alpha0 = __expf(0.125f * (m0 - mn0));
        float alpha1 = __expf(0.125f * (m1 - mn1));
        m0 = mn0; m1 = mn1;
        const float m08 = mn0 * 0.125f, m18 = mn1 * 0.125f;
        float rs0 = 0.f, rs1 = 0.f;
        #pragma unroll
        for (int nt = 0; nt < 8; nt++) {
            s[nt][0] = __expf(fmaf(s[nt][0], 0.125f, -m08));
            s[nt][1] = __expf(fmaf(s[nt][1], 0.125f, -m08));
            s[nt][2] = __expf(fmaf(s[nt][2], 0.125f, -m18));
            s[nt][3] = __expf(fmaf(s[nt][3], 0.125f, -m18));
            rs0 += s[nt][0] + s[nt][1];
            rs1 += s[nt][2] + s[nt][3];
        }
        rs0 += __shfl_xor_sync(0xffffffffu, rs0, 1);
        rs0 += __shfl_xor_sync(0xffffffffu, rs0, 2);
        rs1 += __shfl_xor_sync(0xffffffffu, rs1, 1);
        rs1 += __shfl_xor_sync(0xffffffffu, rs1, 2);
        l0 = l0 * alpha0 + rs0;
        l1 = l1 * alpha1 + rs1;
        #pragma unroll
        for (int nt = 0; nt < 8; nt++) {
            o[nt][0] *= alpha0; o[nt][1] *= alpha0;
            o[nt][2] *= alpha1; o[nt][3] *= alpha1;
        }

        #pragma unroll
        for (int kt = 0; kt < 4; kt++) {
            u32 aph[4], apl[4];
            #pragma unroll
            for (int half = 0; half < 2; half++) {
                const float plo0 = s[2*kt + half][0], phi0 = s[2*kt + half][1];
                const float plo1 = s[2*kt + half][2], phi1 = s[2*kt + half][3];
                u32 h0 = pkbf(phi0, plo0);
                u32 h1 = pkbf(phi1, plo1);
                aph[0 + 2*half] = h0;
                aph[1 + 2*half] = h1;
                apl[0 + 2*half] = pkbf(phi0 - bf_hi(h0), plo0 - bf_lo(h0));
                apl[1 + 2*half] = pkbf(phi1 - bf_hi(h1), plo1 - bf_lo(h1));
            }
            u32 vh4[4][4], vl4[4][4];
            #pragma unroll
            for (int ng2 = 0; ng2 < 4; ng2++) {
                u32 offV = (u32)((kt*16 + lr)*128 + ng2*32 + lhi*16);
                offV ^= (offV >> 3) & 0x70;
                ldsm4t(vh4[ng2][0], vh4[ng2][1], vh4[ng2][2], vh4[ng2][3], sk + 16384 + offV);
                ldsm4t(vl4[ng2][0], vl4[ng2][1], vl4[ng2][2], vl4[ng2][3], sk + 24576 + offV);
            }
            // term 1: Ph * Vh (8 independent MMAs)
            #pragma unroll
            for (int ng2 = 0; ng2 < 4; ng2++) {
                mma16816(o[ng2*2],   aph, vh4[ng2][0], vh4[ng2][1]);
                mma16816(o[ng2*2+1], aph, vh4[ng2][2], vh4[ng2][3]);
            }
            // term 2: Pl * Vh
            #pragma unroll
            for (int ng2 = 0; ng2 < 4; ng2++) {
                mma16816(o[ng2*2],   apl, vh4[ng2][0], vh4[ng2][1]);
                mma16816(o[ng2*2+1], apl, vh4[ng2][2], vh4[ng2][3]);
            }
            // term 3: Ph * Vl
            #pragma unroll
            for (int ng2 = 0; ng2 < 4; ng2++) {
                mma16816(o[ng2*2],   aph, vl4[ng2][0], vl4[ng2][1]);
                mma16816(o[ng2*2+1], aph, vl4[ng2][2], vl4[ng2][3]);
            }
        }
    }

    const float inv0 = 1.f / l0, inv1 = 1.f / l1;
    const size_t orow = (rowbase + q0 + rg) * D_ + colbase;
    #pragma unroll
    for (int nt = 0; nt < 8; nt++) {
        const int col = nt*8 + cq;
        float a0 = o[nt][0]*inv0, a1 = o[nt][1]*inv0;
        float a2 = o[nt][2]*inv1, a3 = o[nt][3]*inv1;
        u32 h01 = pkbf(a1, a0);
        u32 h23 = pkbf(a3, a2);
        u32 l01 = pkbf(a1 - bf_hi(h01), a0 - bf_lo(h01));
        u32 l23 = pkbf(a3 - bf_hi(h23), a2 - bf_lo(h23));
        *(u32*)(oh + orow + col)        = h01;
        *(u32*)(oh + orow + 8*D_ + col) = h23;
        *(u32*)(ol + orow + col)        = l01;
        *(u32*)(ol + orow + 8*D_ + col) = l23;
    }
}

// ---------------------------------------------------------------------------
extern "C" void kernel_launch(void* const* d_in, const int* in_sizes, int n_in,
                              void* d_out, int out_size)
{
    const float* q  = (const float*)d_in[0];
    const float* k  = (const float*)d_in[1];
    const float* v  = (const float*)d_in[2];
    const float* Wq = (const float*)d_in[3];
    const float* bq = (const float*)d_in[4];
    const float* Wk = (const float*)d_in[5];
    const float* bk = (const float*)d_in[6];
    const float* Wv = (const float*)d_in[7];
    const float* bv = (const float*)d_in[8];
    const float* Wo = (const float*)d_in[9];
    const float* bo = (const float*)d_in[10];
    float* out = (float*)d_out;

    __nv_bfloat16 *ih, *il, *wh, *wl, *qhp, *qlp, *khp, *klp, *vhp, *vlp;
    cudaGetSymbolAddress((void**)&ih, g_ih);
    cudaGetSymbolAddress((void**)&il, g_il);
    cudaGetSymbolAddress((void**)&wh, g_wh);
    cudaGetSymbolAddress((void**)&wl, g_wl);
    cudaGetSymbolAddress((void**)&qhp, g_qh);
    cudaGetSymbolAddress((void**)&qlp, g_ql);
    cudaGetSymbolAddress((void**)&khp, g_kh);
    cudaGetSymbolAddress((void**)&klp, g_kl);
    cudaGetSymbolAddress((void**)&vhp, g_vh);
    cudaGetSymbolAddress((void**)&vlp, g_vl);

    const size_t NX = (size_t)M_ * D_;
    const size_t NW = (size_t)D_ * D_;

    cudaFuncSetAttribute(gemm_mma<1>,
                         cudaFuncAttributeMaxDynamicSharedMemorySize, GEMM_SMEM);
    cudaFuncSetAttribute(gemm_mma<0>,
                         cudaFuncAttributeMaxDynamicSharedMemorySize, GEMM_SMEM);
    cudaFuncSetAttribute(flash_attn_mma,
                         cudaFuncAttributeMaxDynamicSharedMemorySize, FA_SMEM);

    // one launch: split q,k,v + all 4 weights into bf16 hi/lo
    CArgs ca = {};
    ca.src[0] = q;  ca.h[0] = ih;        ca.l[0] = il;        ca.n4[0] = (int)(NX/4);
    ca.src[1] = k;  ca.h[1] = ih + NX;   ca.l[1] = il + NX;   ca.n4[1] = (int)(NX/4);
    ca.src[2] = v;  ca.h[2] = ih + 2*NX; ca.l[2] = il + 2*NX; ca.n4[2] = (int)(NX/4);
    ca.src[3] = Wq; ca.h[3] = wh;        ca.l[3] = wl;        ca.n4[3] = (int)(NW/4);
    ca.src[4] = Wk; ca.h[4] = wh + NW;   ca.l[4] = wl + NW;   ca.n4[4] = (int)(NW/4);
    ca.src[5] = Wv; ca.h[5] = wh + 2*NW; ca.l[5] = wl + 2*NW; ca.n4[5] = (int)(NW/4);
    ca.src[6] = Wo; ca.h[6] = wh + 3*NW; ca.l[6] = wl + 3*NW; ca.n4[6] = (int)(NW/4);
    cvt_split7<<<dim3((unsigned)(NX/4/256), 7), 256>>>(ca);

    // fused Q/K/V projections, cp.async double-buffered
    GArgs2 gq = {};
    gq.Ah[0] = ih;        gq.Al[0] = il;        gq.Wh[0] = wh;        gq.Wl[0] = wl;
    gq.Ah[1] = ih + NX;   gq.Al[1] = il + NX;   gq.Wh[1] = wh + NW;   gq.Wl[1] = wl + NW;
    gq.Ah[2] = ih + 2*NX; gq.Al[2] = il + 2*NX; gq.Wh[2] = wh + 2*NW; gq.Wl[2] = wl + 2*NW;
    gq.bias[0] = bq; gq.bias[1] = bk; gq.bias[2] = bv;
    gq.Ch[0] = qhp; gq.Ch[1] = khp; gq.Ch[2] = vhp;
    gq.Cl[0] = qlp; gq.Cl[1] = klp; gq.Cl[2] = vlp;
    gemm_mma<1><<<dim3(D_/128, M_/128, 3), 256, GEMM_SMEM>>>(gq);

    // attention: writes bf16 hi/lo splits into the (now free) q-input buffers
    flash_attn_mma<<<dim3(S_/128, B_*H_), 256, FA_SMEM>>>(qhp, qlp, khp, klp,
                                                           vhp, vlp, ih, il);

    // output projection (fp32 out)
    GArgs2 go = {};
    go.Ah[0] = ih; go.Al[0] = il;
    go.Wh[0] = wh + 3*NW; go.Wl[0] = wl + 3*NW;
    go.bias[0] = bo;
    go.Cf[0] = out;
    gemm_mma<0><<<dim3(D_/128, M_/128, 1), 256, GEMM_SMEM>>>(go);
}